// round 15
// baseline (speedup 1.0000x reference)
#include <cuda_runtime.h>
#include <cuda_bf16.h>
#include <cstdint>
#include <cstddef>
#include <math.h>

// Problem constants
#define B_   2
#define S_   2048
#define HID_ 2048
#define NH_  16
#define HD_  128
#define M_   (B_ * S_)     // 4096
#define K_   HID_          // 2048
#define KEX_ (3 * K_)      // 6144 expanded (hi|lo|hi split)

// ---------------------------------------------------------------------------
// Scratch (allocation-free rule: __device__ globals)
// ---------------------------------------------------------------------------
__device__ float g_q[B_ * NH_ * S_ * HD_];     // [b,h,s,d] fp32
__device__ float g_k[B_ * NH_ * S_ * HD_];
__device__ float g_v[B_ * NH_ * S_ * HD_];

__device__ __nv_bfloat16 g_aex[(size_t)M_ * KEX_];
__device__ __nv_bfloat16 g_cex[(size_t)M_ * KEX_];
__device__ __nv_bfloat16 g_wqe[(size_t)HID_ * KEX_];
__device__ __nv_bfloat16 g_wke[(size_t)HID_ * KEX_];
__device__ __nv_bfloat16 g_wve[(size_t)HID_ * KEX_];
__device__ __nv_bfloat16 g_woe[(size_t)HID_ * KEX_];

// flash operands: hi/lo bf16
__device__ __nv_bfloat16 g_qh[B_ * NH_ * S_ * HD_];   // [b,h,s,d]
__device__ __nv_bfloat16 g_ql[B_ * NH_ * S_ * HD_];
__device__ __nv_bfloat16 g_kh[B_ * NH_ * S_ * HD_];
__device__ __nv_bfloat16 g_kl[B_ * NH_ * S_ * HD_];
__device__ __nv_bfloat16 g_vth[B_ * NH_ * S_ * HD_];  // [b,h,d,s] (transposed)
__device__ __nv_bfloat16 g_vtl[B_ * NH_ * S_ * HD_];

// ---------------------------------------------------------------------------
// fp32 -> bf16 hi/lo split, expanded-K layout (vectorized).
// mode 0 (A side): [hi | lo | hi];  mode 1 (W side): [hi | hi | lo]
// ---------------------------------------------------------------------------
__device__ __forceinline__ void split4(const float* __restrict__ X,
                                       __nv_bfloat16* __restrict__ Y,
                                       int t, int mode)
{
    const int idx = t * 4;
    const int r = idx >> 11;
    const int k = idx & (K_ - 1);
    const float4 x = *(const float4*)(X + idx);

    __nv_bfloat16 hi[4], lo[4];
    const float xs[4] = {x.x, x.y, x.z, x.w};
#pragma unroll
    for (int i = 0; i < 4; i++) {
        hi[i] = __float2bfloat16_rn(xs[i]);
        lo[i] = __float2bfloat16_rn(xs[i] - __bfloat162float(hi[i]));
    }
    __nv_bfloat16* dst = Y + (size_t)r * KEX_ + k;
    *(uint2*)(dst) = *(const uint2*)hi;
    if (mode == 0) {
        *(uint2*)(dst + K_)     = *(const uint2*)lo;
        *(uint2*)(dst + 2 * K_) = *(const uint2*)hi;
    } else {
        *(uint2*)(dst + K_)     = *(const uint2*)hi;
        *(uint2*)(dst + 2 * K_) = *(const uint2*)lo;
    }
}

// Merged: 4 weights (grid.y 0..3, W-mode) + hidden-states A (grid.y 4, A-mode,
// two nW4-sized chunks since nA4 == 2*nW4).
__global__ void split_all(const float* __restrict__ hs,
                          const float* __restrict__ Wq, const float* __restrict__ Wk,
                          const float* __restrict__ Wv, const float* __restrict__ Wo,
                          __nv_bfloat16* __restrict__ Ya,
                          __nv_bfloat16* __restrict__ Yq, __nv_bfloat16* __restrict__ Yk,
                          __nv_bfloat16* __restrict__ Yv, __nv_bfloat16* __restrict__ Yo,
                          int totalW4)
{
    const int t = blockIdx.x * blockDim.x + threadIdx.x;
    if (t >= totalW4) return;
    const int sel = blockIdx.y;
    if (sel == 4) {
        split4(hs, Ya, t, 0);
        split4(hs, Ya, t + totalW4, 0);
        return;
    }
    const float* X = (sel == 0) ? Wq : (sel == 1) ? Wk : (sel == 2) ? Wv : Wo;
    __nv_bfloat16* Y = (sel == 0) ? Yq : (sel == 1) ? Yk : (sel == 2) ? Yv : Yo;
    split4(X, Y, t, 1);
}

// ---------------------------------------------------------------------------
// mma / cp.async helpers
// ---------------------------------------------------------------------------
__device__ __forceinline__ void cpasync16(unsigned int smem_dst, const void* gsrc) {
    asm volatile("cp.async.cg.shared.global [%0], [%1], 16;\n" :: "r"(smem_dst), "l"(gsrc));
}
__device__ __forceinline__ void cp_commit() {
    asm volatile("cp.async.commit_group;\n");
}
__device__ __forceinline__ void ldm_x4(unsigned int& r0, unsigned int& r1,
                                       unsigned int& r2, unsigned int& r3,
                                       unsigned int addr) {
    asm volatile("ldmatrix.sync.aligned.m8n8.x4.shared.b16 {%0,%1,%2,%3}, [%4];\n"
                 : "=r"(r0), "=r"(r1), "=r"(r2), "=r"(r3) : "r"(addr));
}
__device__ __forceinline__ void mma_bf16(float* c, const unsigned int* a,
                                         const unsigned int* b) {
    asm volatile(
        "mma.sync.aligned.m16n8k16.row.col.f32.bf16.bf16.f32 "
        "{%0,%1,%2,%3}, {%4,%5,%6,%7}, {%8,%9}, {%0,%1,%2,%3};\n"
        : "+f"(c[0]), "+f"(c[1]), "+f"(c[2]), "+f"(c[3])
        : "r"(a[0]), "r"(a[1]), "r"(a[2]), "r"(a[3]), "r"(b[0]), "r"(b[1]));
}

__device__ __forceinline__ unsigned int pack_hi2(float a, float b,
                                                 unsigned int& lo_pack) {
    const __nv_bfloat16 h0 = __float2bfloat16_rn(a);
    const __nv_bfloat16 h1 = __float2bfloat16_rn(b);
    const __nv_bfloat16 g0 = __float2bfloat16_rn(a - __bfloat162float(h0));
    const __nv_bfloat16 g1 = __float2bfloat16_rn(b - __bfloat162float(h1));
    lo_pack = ((unsigned int)__bfloat16_as_ushort(g1) << 16) | __bfloat16_as_ushort(g0);
    return ((unsigned int)__bfloat16_as_ushort(h1) << 16) | __bfloat16_as_ushort(h0);
}

// ---------------------------------------------------------------------------
// GEMM configuration (proven R5/R8 shape)
// ---------------------------------------------------------------------------
#define GBM 128
#define GBN 128
#define GBK 64
#define LDP 72
#define GSTG 3
#define STG_B (GBM * LDP * 2)
#define GEMM_SMEM (2 * GSTG * STG_B)

// ---------------------------------------------------------------------------
// Fused QKV GEMM: one launch, grid (48, 32). n-block selects weight + dest.
// ---------------------------------------------------------------------------
__global__ __launch_bounds__(256, 2)
void gemm_qkv(const __nv_bfloat16* __restrict__ A,
              const __nv_bfloat16* __restrict__ Wq,
              const __nv_bfloat16* __restrict__ Wk,
              const __nv_bfloat16* __restrict__ Wv,
              float* __restrict__ Cq, float* __restrict__ Ck,
              float* __restrict__ Cv)
{
    extern __shared__ char gsm[];
    const unsigned int sbase = (unsigned int)__cvta_generic_to_shared(gsm);
    const unsigned int sBoff = GSTG * STG_B;

    const int tid  = threadIdx.x;
    const int lane = tid & 31;
    const int w    = tid >> 5;
    const int wm   = (w >> 1) << 5;
    const int wn   = (w & 1) << 6;
    const int m0   = blockIdx.y * GBM;
    const int ng   = blockIdx.x * GBN;
    const int which = ng >> 11;
    const int n0   = ng & (K_ - 1);

    const __nv_bfloat16* W = (which == 0) ? Wq : (which == 1) ? Wk : Wv;
    float* C = (which == 0) ? Cq : (which == 1) ? Ck : Cv;

    float acc[2][8][4];
#pragma unroll
    for (int mi = 0; mi < 2; mi++)
#pragma unroll
        for (int ni = 0; ni < 8; ni++)
#pragma unroll
            for (int e = 0; e < 4; e++) acc[mi][ni][e] = 0.0f;

    const int lr = tid >> 3;
    const int lc = tid & 7;
    const int NT = KEX_ / GBK;

    auto load_stage = [&](int kt, int s) {
        const unsigned int aD = sbase + s * STG_B;
        const unsigned int bD = sbase + sBoff + s * STG_B;
        const __nv_bfloat16* Ap = A + (size_t)m0 * KEX_ + kt * GBK + lc * 8;
        const __nv_bfloat16* Wp = W + (size_t)n0 * KEX_ + kt * GBK + lc * 8;
#pragma unroll
        for (int i = 0; i < 4; i++) {
            const int row = lr + i * 32;
            const unsigned int off = (unsigned int)(row * LDP + lc * 8) * 2;
            cpasync16(aD + off, Ap + (size_t)row * KEX_);
            cpasync16(bD + off, Wp + (size_t)row * KEX_);
        }
        cp_commit();
    };

    load_stage(0, 0);
    load_stage(1, 1);

    for (int kt = 0; kt < NT; kt++) {
        if (kt + 1 < NT) {
            asm volatile("cp.async.wait_group 1;\n");
        } else {
            asm volatile("cp.async.wait_group 0;\n");
        }
        __syncthreads();

        if (kt + 2 < NT) load_stage(kt + 2, (kt + 2) % GSTG);

        const int s = kt % GSTG;
        const unsigned int aBase = sbase + s * STG_B;
        const unsigned int bBase = sbase + sBoff + s * STG_B;

#pragma unroll
        for (int ks = 0; ks < 4; ks++) {
            unsigned int afr[2][4], bfr[8][2];
#pragma unroll
            for (int mi = 0; mi < 2; mi++) {
                const int row = wm + mi * 16 + (lane & 15);
                const unsigned int addr =
                    aBase + (unsigned int)(row * LDP + ks * 16 + (lane >> 4) * 8) * 2;
                ldm_x4(afr[mi][0], afr[mi][1], afr[mi][2], afr[mi][3], addr);
            }
#pragma unroll
            for (int p = 0; p < 4; p++) {
                const int nrow = wn + p * 16 + (lane & 7) + ((lane >> 4) << 3);
                const int chunk = (lane >> 3) & 1;
                const unsigned int addr =
                    bBase + (unsigned int)(nrow * LDP + ks * 16 + chunk * 8) * 2;
                ldm_x4(bfr[2 * p][0], bfr[2 * p][1], bfr[2 * p + 1][0], bfr[2 * p + 1][1], addr);
            }
#pragma unroll
            for (int mi = 0; mi < 2; mi++)
#pragma unroll
                for (int ni = 0; ni < 8; ni++)
                    mma_bf16(acc[mi][ni], afr[mi], bfr[ni]);
        }
    }

#pragma unroll
    for (int mi = 0; mi < 2; mi++) {
#pragma unroll
        for (int ni = 0; ni < 8; ni++) {
            const int rr = m0 + wm + mi * 16 + (lane >> 2);
            const int cc = n0 + wn + ni * 8 + ((lane & 3) << 1);
#pragma unroll
            for (int e = 0; e < 4; e++) {
                const int m = rr + ((e >> 1) << 3);
                const int n = cc + (e & 1);
                const int b = m >> 11, s2 = m & (S_ - 1);
                const int h = n >> 7,  d = n & (HD_ - 1);
                C[(((size_t)(b * NH_ + h)) * S_ + s2) * HD_ + d] = acc[mi][ni][e];
            }
        }
    }
}

// ---------------------------------------------------------------------------
// Plain GEMM (Wo projection, layout 0).
// ---------------------------------------------------------------------------
__global__ __launch_bounds__(256, 2)
void gemm_bf16(const __nv_bfloat16* __restrict__ A,
               const __nv_bfloat16* __restrict__ W,
               float* __restrict__ C, int N, int Kex)
{
    extern __shared__ char gsm[];
    const unsigned int sbase = (unsigned int)__cvta_generic_to_shared(gsm);
    const unsigned int sBoff = GSTG * STG_B;

    const int tid  = threadIdx.x;
    const int lane = tid & 31;
    const int w    = tid >> 5;
    const int wm   = (w >> 1) << 5;
    const int wn   = (w & 1) << 6;
    const int m0   = blockIdx.y * GBM;
    const int n0   = blockIdx.x * GBN;

    float acc[2][8][4];
#pragma unroll
    for (int mi = 0; mi < 2; mi++)
#pragma unroll
        for (int ni = 0; ni < 8; ni++)
#pragma unroll
            for (int e = 0; e < 4; e++) acc[mi][ni][e] = 0.0f;

    const int lr = tid >> 3;
    const int lc = tid & 7;
    const int NT = Kex / GBK;

    auto load_stage = [&](int kt, int s) {
        const unsigned int aD = sbase + s * STG_B;
        const unsigned int bD = sbase + sBoff + s * STG_B;
        const __nv_bfloat16* Ap = A + (size_t)m0 * Kex + kt * GBK + lc * 8;
        const __nv_bfloat16* Wp = W + (size_t)n0 * Kex + kt * GBK + lc * 8;
#pragma unroll
        for (int i = 0; i < 4; i++) {
            const int row = lr + i * 32;
            const unsigned int off = (unsigned int)(row * LDP + lc * 8) * 2;
            cpasync16(aD + off, Ap + (size_t)row * Kex);
            cpasync16(bD + off, Wp + (size_t)row * Kex);
        }
        cp_commit();
    };

    load_stage(0, 0);
    load_stage(1, 1);

    for (int kt = 0; kt < NT; kt++) {
        if (kt + 1 < NT) {
            asm volatile("cp.async.wait_group 1;\n");
        } else {
            asm volatile("cp.async.wait_group 0;\n");
        }
        __syncthreads();

        if (kt + 2 < NT) load_stage(kt + 2, (kt + 2) % GSTG);

        const int s = kt % GSTG;
        const unsigned int aBase = sbase + s * STG_B;
        const unsigned int bBase = sbase + sBoff + s * STG_B;

#pragma unroll
        for (int ks = 0; ks < 4; ks++) {
            unsigned int afr[2][4], bfr[8][2];
#pragma unroll
            for (int mi = 0; mi < 2; mi++) {
                const int row = wm + mi * 16 + (lane & 15);
                const unsigned int addr =
                    aBase + (unsigned int)(row * LDP + ks * 16 + (lane >> 4) * 8) * 2;
                ldm_x4(afr[mi][0], afr[mi][1], afr[mi][2], afr[mi][3], addr);
            }
#pragma unroll
            for (int p = 0; p < 4; p++) {
                const int nrow = wn + p * 16 + (lane & 7) + ((lane >> 4) << 3);
                const int chunk = (lane >> 3) & 1;
                const unsigned int addr =
                    bBase + (unsigned int)(nrow * LDP + ks * 16 + chunk * 8) * 2;
                ldm_x4(bfr[2 * p][0], bfr[2 * p][1], bfr[2 * p + 1][0], bfr[2 * p + 1][1], addr);
            }
#pragma unroll
            for (int mi = 0; mi < 2; mi++)
#pragma unroll
                for (int ni = 0; ni < 8; ni++)
                    mma_bf16(acc[mi][ni], afr[mi], bfr[ni]);
        }
    }

#pragma unroll
    for (int mi = 0; mi < 2; mi++) {
#pragma unroll
        for (int ni = 0; ni < 8; ni++) {
            const int rr = m0 + wm + mi * 16 + (lane >> 2);
            const int cc = n0 + wn + ni * 8 + ((lane & 3) << 1);
#pragma unroll
            for (int e = 0; e < 4; e++) {
                const int m = rr + ((e >> 1) << 3);
                const int n = cc + (e & 1);
                C[(size_t)m * N + n] = acc[mi][ni][e];
            }
        }
    }
}

// ---------------------------------------------------------------------------
// Merged RoPE-split + V-transpose-split, one launch.
// Blocks [0, RS_BLKS) run the rope path; [RS_BLKS, RS_BLKS+VT_BLKS) transpose V.
// Both bodies byte-identical to the R14 standalone kernels.
// ---------------------------------------------------------------------------
#define RS_BLKS ((B_ * NH_ * S_ * 32) / 256)                 // 4096
#define VT_BLKS ((S_ / 32) * (HD_ / 32) * (B_ * NH_))        // 8192

__global__ void prep_qkv(const float* __restrict__ q, const float* __restrict__ k,
                         const float* __restrict__ v,
                         const int* __restrict__ pos_ids,
                         __nv_bfloat16* __restrict__ qh, __nv_bfloat16* __restrict__ ql,
                         __nv_bfloat16* __restrict__ kh, __nv_bfloat16* __restrict__ kl,
                         __nv_bfloat16* __restrict__ vth, __nv_bfloat16* __restrict__ vtl)
{
    if (blockIdx.x < RS_BLKS) {
        // ---- RoPE + split path (256 threads, pair-vectorized) ----
        const int idx = blockIdx.x * 256 + threadIdx.x;
        const int d = (idx & 31) << 1;
        int t = idx >> 5;
        const int s = t & (S_ - 1);
        t >>= 11;
        const int h = t & (NH_ - 1);
        const int b = t >> 4;

        const int p = pos_ids[b * S_ + s];
        const size_t base = (((size_t)(b * NH_ + h)) * S_ + s) * HD_ + d;

        const float2 q1 = *(const float2*)&q[base];
        const float2 q2 = *(const float2*)&q[base + 64];
        const float2 k1 = *(const float2*)&k[base];
        const float2 k2 = *(const float2*)&k[base + 64];

        float rq1[2], rq2[2], rk1[2], rk2[2];
#pragma unroll
        for (int j = 0; j < 2; j++) {
            const float ee = (float)(-(2 * (d + j))) * 0.10381025296523008f;
            const float ang = (float)p * exp2f(ee);
            float sn, cs;
            sincosf(ang, &sn, &cs);
            const float x1 = j ? q1.y : q1.x, x2 = j ? q2.y : q2.x;
            const float y1 = j ? k1.y : k1.x, y2 = j ? k2.y : k2.x;
            rq1[j] = x1 * cs - x2 * sn;  rq2[j] = x2 * cs + x1 * sn;
            rk1[j] = y1 * cs - y2 * sn;  rk2[j] = y2 * cs + y1 * sn;
        }

        unsigned int lo;
        *(unsigned int*)&qh[base]      = pack_hi2(rq1[0], rq1[1], lo); *(unsigned int*)&ql[base]      = lo;
        *(unsigned int*)&qh[base + 64] = pack_hi2(rq2[0], rq2[1], lo); *(unsigned int*)&ql[base + 64] = lo;
        *(unsigned int*)&kh[base]      = pack_hi2(rk1[0], rk1[1], lo); *(unsigned int*)&kl[base]      = lo;
        *(unsigned int*)&kh[base + 64] = pack_hi2(rk2[0], rk2[1], lo); *(unsigned int*)&kl[base + 64] = lo;
    } else {
        // ---- V transpose + split path ----
        __shared__ float tile[32][33];
        const int blk = blockIdx.x - RS_BLKS;
        const int sp  = S_ / 32;              // 64 s-tiles
        const int dp  = HD_ / 32;             // 4  d-tiles
        const int bh  = blk / (sp * dp);
        const int rem = blk % (sp * dp);
        const int d0  = (rem / sp) * 32;
        const int s0  = (rem % sp) * 32;
        const int tx = threadIdx.x & 31;
        const int ty = threadIdx.x >> 5;      // 0..7
#pragma unroll
        for (int i = 0; i < 4; i++) {
            const int sr = ty * 4 + i;
            tile[sr][tx] = v[(((size_t)bh * S_) + s0 + sr) * HD_ + d0 + tx];
        }
        __syncthreads();

        const int nt = ty * 32 + tx;
        const int sc2 = nt & 15;
        const int dr0 = nt >> 4;
#pragma unroll
        for (int i = 0; i < 2; i++) {
            const int dr = dr0 + i * 16;
            const float v0 = tile[2 * sc2][dr];
            const float v1 = tile[2 * sc2 + 1][dr];
            unsigned int lo;
            const unsigned int hi = pack_hi2(v0, v1, lo);
            const size_t o = (((size_t)bh * HD_) + d0 + dr) * S_ + s0 + 2 * sc2;
            *(unsigned int*)&vth[o] = hi;
            *(unsigned int*)&vtl[o] = lo;
        }
    }
}

// ---------------------------------------------------------------------------
// Flash attention on tensor cores (bf16 hi/lo 3-term splits, fp32 softmax).
// 64 q-rows per CTA, 4 warps, 64-kv tiles, HD=128. LPT scheduling.
// Epilogue writes cex (hi|lo|hi expanded) directly with packed 4B stores.
// ---------------------------------------------------------------------------
#define FS_QH 0
#define FS_QL 17408
#define FS_KH 34816
#define FS_KL 52224
#define FS_VH 69632
#define FS_VL 88064
#define FSMEM_TOTAL 106496

__global__ __launch_bounds__(128, 2)
void flash_mma(const __nv_bfloat16* __restrict__ qh_g, const __nv_bfloat16* __restrict__ ql_g,
               const __nv_bfloat16* __restrict__ kh_g, const __nv_bfloat16* __restrict__ kl_g,
               const __nv_bfloat16* __restrict__ vth_g, const __nv_bfloat16* __restrict__ vtl_g,
               __nv_bfloat16* __restrict__ cex)
{
    extern __shared__ char fsm[];
    const unsigned int sb = (unsigned int)__cvta_generic_to_shared(fsm);
    const int tid  = threadIdx.x;
    const int lane = tid & 31;
    const int w    = tid >> 5;
    const int qt   = (S_ / 64 - 1) - blockIdx.x;   // longest-first (LPT)
    const int bh   = blockIdx.y;

    // preload Q tiles (hi + lo)
    {
        const size_t qoff = (((size_t)bh * S_) + qt * 64) * HD_;
#pragma unroll
        for (int i = 0; i < 8; i++) {
            const int idx = tid + i * 128;
            const int row = idx >> 4, c = idx & 15;
            const unsigned int off = (unsigned int)(row * 136 + c * 8) * 2;
            cpasync16(sb + FS_QH + off, qh_g + qoff + (size_t)row * HD_ + c * 8);
            cpasync16(sb + FS_QL + off, ql_g + qoff + (size_t)row * HD_ + c * 8);
        }
        cp_commit();
    }

    float oacc[16][4];
#pragma unroll
    for (int ni = 0; ni < 16; ni++)
#pragma unroll
        for (int e = 0; e < 4; e++) oacc[ni][e] = 0.0f;
    float m_i[2] = {-3.0e30f, -3.0e30f};
    float l_i[2] = {0.0f, 0.0f};

    const float SCALE = 0.08838834764831845f;   // 1/sqrt(128)

    for (int j = 0; j <= qt; j++) {
        {
            const size_t koff = (((size_t)bh * S_) + j * 64) * HD_;
            const size_t voff = ((size_t)bh * HD_) * S_ + j * 64;
#pragma unroll
            for (int i = 0; i < 8; i++) {
                const int idx = tid + i * 128;
                const int r16 = idx >> 4, c16 = idx & 15;
                const unsigned int offk = (unsigned int)(r16 * 136 + c16 * 8) * 2;
                cpasync16(sb + FS_KH + offk, kh_g + koff + (size_t)r16 * HD_ + c16 * 8);
                cpasync16(sb + FS_KL + offk, kl_g + koff + (size_t)r16 * HD_ + c16 * 8);
                const int r8 = idx >> 3, c8 = idx & 7;
                const unsigned int offv = (unsigned int)(r8 * 72 + c8 * 8) * 2;
                cpasync16(sb + FS_VH + offv, vth_g + voff + (size_t)r8 * S_ + c8 * 8);
                cpasync16(sb + FS_VL + offv, vtl_g + voff + (size_t)r8 * S_ + c8 * 8);
            }
            cp_commit();
        }
        asm volatile("cp.async.wait_group 0;\n");
        __syncthreads();

        // ---- scores: S = Qh·Kh^T + Ql·Kh^T + Qh·Kl^T ----
        float sreg[8][4];
#pragma unroll
        for (int ni = 0; ni < 8; ni++)
#pragma unroll
            for (int e = 0; e < 4; e++) sreg[ni][e] = 0.0f;

#pragma unroll
        for (int kt = 0; kt < 8; kt++) {
            unsigned int qfh[4], qfl[4], bfh[8][2], bfl[8][2];
            const int arow = w * 16 + (lane & 15);
            const unsigned int aoff = (unsigned int)(arow * 136 + kt * 16 + (lane >> 4) * 8) * 2;
            ldm_x4(qfh[0], qfh[1], qfh[2], qfh[3], sb + FS_QH + aoff);
            ldm_x4(qfl[0], qfl[1], qfl[2], qfl[3], sb + FS_QL + aoff);
#pragma unroll
            for (int p = 0; p < 4; p++) {
                const int nrow = p * 16 + (lane & 7) + ((lane >> 4) << 3);
                const unsigned int boff =
                    (unsigned int)(nrow * 136 + kt * 16 + ((lane >> 3) & 1) * 8) * 2;
                ldm_x4(bfh[2*p][0], bfh[2*p][1], bfh[2*p+1][0], bfh[2*p+1][1], sb + FS_KH + boff);
                ldm_x4(bfl[2*p][0], bfl[2*p][1], bfl[2*p+1][0], bfl[2*p+1][1], sb + FS_KL + boff);
            }
#pragma unroll
            for (int ni = 0; ni < 8; ni++) mma_bf16(sreg[ni], qfh, bfh[ni]);
#pragma unroll
            for (int ni = 0; ni < 8; ni++) mma_bf16(sreg[ni], qfl, bfh[ni]);
#pragma unroll
            for (int ni = 0; ni < 8; ni++) mma_bf16(sreg[ni], qfh, bfl[ni]);
        }

        // ---- scale + causal mask ----
        const bool diag = (j == qt);
        const int r0 = lane >> 2;
        const int c0 = (lane & 3) << 1;
#pragma unroll
        for (int ni = 0; ni < 8; ni++)
#pragma unroll
            for (int e = 0; e < 4; e++) {
                sreg[ni][e] *= SCALE;
                if (diag) {
                    const int qrow = w * 16 + r0 + ((e >> 1) << 3);
                    const int kcol = ni * 8 + c0 + (e & 1);
                    if (kcol > qrow) sreg[ni][e] = -1.0e30f;
                }
            }

        // ---- online softmax ----
        float corr[2];
#pragma unroll
        for (int h2 = 0; h2 < 2; h2++) {
            const int e0 = h2 * 2;
            float mloc = -3.0e30f;
#pragma unroll
            for (int ni = 0; ni < 8; ni++)
                mloc = fmaxf(mloc, fmaxf(sreg[ni][e0], sreg[ni][e0 + 1]));
            mloc = fmaxf(mloc, __shfl_xor_sync(0xffffffffu, mloc, 1));
            mloc = fmaxf(mloc, __shfl_xor_sync(0xffffffffu, mloc, 2));
            const float mnew = fmaxf(m_i[h2], mloc);
            corr[h2] = __expf(m_i[h2] - mnew);
            m_i[h2] = mnew;
            float lloc = 0.0f;
#pragma unroll
            for (int ni = 0; ni < 8; ni++) {
                const float p0 = __expf(sreg[ni][e0]     - mnew);
                const float p1 = __expf(sreg[ni][e0 + 1] - mnew);
                sreg[ni][e0] = p0; sreg[ni][e0 + 1] = p1;
                lloc += p0 + p1;
            }
            lloc += __shfl_xor_sync(0xffffffffu, lloc, 1);
            lloc += __shfl_xor_sync(0xffffffffu, lloc, 2);
            l_i[h2] = l_i[h2] * corr[h2] + lloc;
        }
#pragma unroll
        for (int ni = 0; ni < 16; ni++)
#pragma unroll
            for (int e = 0; e < 4; e++) oacc[ni][e] *= corr[e >> 1];

        // ---- repack P into A-fragments (hi/lo) ----
        unsigned int pah[4][4], pal[4][4];
#pragma unroll
        for (int t = 0; t < 4; t++) {
#pragma unroll
            for (int rix = 0; rix < 4; rix++) {
                const int ni = 2 * t + (rix >> 1);
                const int eb = (rix & 1) * 2;
                pah[t][rix] = pack_hi2(sreg[ni][eb], sreg[ni][eb + 1], pal[t][rix]);
            }
        }

        // ---- O += Ph·Vh + Pl·Vh + Ph·Vl ----
#pragma unroll
        for (int t = 0; t < 4; t++) {
            unsigned int bvh[16][2], bvl[16][2];
#pragma unroll
            for (int p = 0; p < 8; p++) {
                const int nrow = p * 16 + (lane & 7) + ((lane >> 4) << 3);
                const unsigned int boff =
                    (unsigned int)(nrow * 72 + t * 16 + ((lane >> 3) & 1) * 8) * 2;
                ldm_x4(bvh[2*p][0], bvh[2*p][1], bvh[2*p+1][0], bvh[2*p+1][1], sb + FS_VH + boff);
                ldm_x4(bvl[2*p][0], bvl[2*p][1], bvl[2*p+1][0], bvl[2*p+1][1], sb + FS_VL + boff);
            }
#pragma unroll
            for (int ni = 0; ni < 16; ni++) mma_bf16(oacc[ni], pah[t], bvh[ni]);
#pragma unroll
            for (int ni = 0; ni < 16; ni++) mma_bf16(oacc[ni], pal[t], bvh[ni]);
#pragma unroll
            for (int ni = 0; ni < 16; ni++) mma_bf16(oacc[ni], pah[t], bvl[ni]);
        }
        __syncthreads();   // before next j overwrites K/V smem
    }

    // ---- epilogue: write cex (hi|lo|hi) directly, packed 4B stores ----
    const float linv[2] = {1.0f / l_i[0], 1.0f / l_i[1]};
    const int b = bh >> 4;
    const int h = bh & (NH_ - 1);
    const int d0base = (lane & 3) << 1;
#pragma unroll
    for (int ni = 0; ni < 16; ni++) {
#pragma unroll
        for (int half = 0; half < 2; half++) {
            const int e0 = half * 2;
            const int qrow = qt * 64 + w * 16 + (lane >> 2) + half * 8;
            const int d0 = ni * 8 + d0base;
            const float v0 = oacc[ni][e0]     * linv[half];
            const float v1 = oacc[ni][e0 + 1] * linv[half];
            unsigned int lo;
            const unsigned int hi = pack_hi2(v0, v1, lo);
            __nv_bfloat16* dst =
                cex + ((size_t)b * S_ + qrow) * KEX_ + h * HD_ + d0;
            *(unsigned int*)(dst)          = hi;
            *(unsigned int*)(dst + K_)     = lo;
            *(unsigned int*)(dst + 2 * K_) = hi;
        }
    }
}

// ---------------------------------------------------------------------------
extern "C" void kernel_launch(void* const* d_in, const int* in_sizes, int n_in,
                              void* d_out, int out_size)
{
    const float* hs  = (const float*)d_in[0];
    // d_in[1] = attention_mask: deterministically causal, applied analytically
    const int*   pos = (const int*)d_in[2];
    const float* Wq  = (const float*)d_in[3];
    const float* Wk  = (const float*)d_in[4];
    const float* Wv  = (const float*)d_in[5];
    const float* Wo  = (const float*)d_in[6];
    float* out = (float*)d_out;

    float *q, *k, *v;
    __nv_bfloat16 *aex, *cex, *wqe, *wke, *wve, *woe;
    __nv_bfloat16 *qh, *ql, *kh, *kl, *vth, *vtl;
    cudaGetSymbolAddress((void**)&q,   g_q);
    cudaGetSymbolAddress((void**)&k,   g_k);
    cudaGetSymbolAddress((void**)&v,   g_v);
    cudaGetSymbolAddress((void**)&aex, g_aex);
    cudaGetSymbolAddress((void**)&cex, g_cex);
    cudaGetSymbolAddress((void**)&wqe, g_wqe);
    cudaGetSymbolAddress((void**)&wke, g_wke);
    cudaGetSymbolAddress((void**)&wve, g_wve);
    cudaGetSymbolAddress((void**)&woe, g_woe);
    cudaGetSymbolAddress((void**)&qh,  g_qh);
    cudaGetSymbolAddress((void**)&ql,  g_ql);
    cudaGetSymbolAddress((void**)&kh,  g_kh);
    cudaGetSymbolAddress((void**)&kl,  g_kl);
    cudaGetSymbolAddress((void**)&vth, g_vth);
    cudaGetSymbolAddress((void**)&vtl, g_vtl);

    const int nW4 = (HID_ * K_) / 4;
    // one launch: 4 weights + hidden states
    split_all<<<dim3((nW4 + 255) / 256, 5), 256>>>(hs, Wq, Wk, Wv, Wo,
                                                   aex, wqe, wke, wve, woe, nW4);

    static bool attr_set = false;
    if (!attr_set) {
        cudaFuncSetAttribute(gemm_qkv,  cudaFuncAttributeMaxDynamicSharedMemorySize, GEMM_SMEM);
        cudaFuncSetAttribute(gemm_bf16, cudaFuncAttributeMaxDynamicSharedMemorySize, GEMM_SMEM);
        cudaFuncSetAttribute(flash_mma, cudaFuncAttributeMaxDynamicSharedMemorySize, FSMEM_TOTAL);
        attr_set = true;
    }

    // fused QKV projection: one launch, grid (48, 32)
    gemm_qkv<<<dim3(3 * HID_ / GBN, M_ / GBM), 256, GEMM_SMEM>>>(
        aex, wqe, wke, wve, q, k, v);

    // merged RoPE-split + V-transpose-split: one launch
    prep_qkv<<<RS_BLKS + VT_BLKS, 256>>>(q, k, v, pos, qh, ql, kh, kl, vth, vtl);

    // flash attention writes cex (expanded) directly
    flash_mma<<<dim3(S_ / 64, B_ * NH_), 128, FSMEM_TOTAL>>>(qh, ql, kh, kl, vth, vtl, cex);

    gemm_bf16<<<dim3(HID_ / GBN, M_ / GBM), 256, GEMM_SMEM>>>(cex, woe, out, HID_, KEX_);
}

// round 16
// speedup vs baseline: 1.0088x; 1.0088x over previous
#include <cuda_runtime.h>
#include <cuda_bf16.h>
#include <cstdint>
#include <cstddef>
#include <math.h>

// Problem constants
#define B_   2
#define S_   2048
#define HID_ 2048
#define NH_  16
#define HD_  128
#define M_   (B_ * S_)     // 4096
#define K_   HID_          // 2048
#define KEX_ (3 * K_)      // 6144 expanded (hi|lo|hi split)

// ---------------------------------------------------------------------------
// Scratch (allocation-free rule: __device__ globals)
// ---------------------------------------------------------------------------
__device__ float g_q[B_ * NH_ * S_ * HD_];     // [b,h,s,d] fp32
__device__ float g_k[B_ * NH_ * S_ * HD_];
__device__ float g_v[B_ * NH_ * S_ * HD_];

__device__ __nv_bfloat16 g_aex[(size_t)M_ * KEX_];
__device__ __nv_bfloat16 g_cex[(size_t)M_ * KEX_];
__device__ __nv_bfloat16 g_wqe[(size_t)HID_ * KEX_];
__device__ __nv_bfloat16 g_wke[(size_t)HID_ * KEX_];
__device__ __nv_bfloat16 g_wve[(size_t)HID_ * KEX_];
__device__ __nv_bfloat16 g_woe[(size_t)HID_ * KEX_];

// flash operands: hi/lo bf16
__device__ __nv_bfloat16 g_qh[B_ * NH_ * S_ * HD_];   // [b,h,s,d]
__device__ __nv_bfloat16 g_ql[B_ * NH_ * S_ * HD_];
__device__ __nv_bfloat16 g_kh[B_ * NH_ * S_ * HD_];
__device__ __nv_bfloat16 g_kl[B_ * NH_ * S_ * HD_];
__device__ __nv_bfloat16 g_vth[B_ * NH_ * S_ * HD_];  // [b,h,d,s] (transposed)
__device__ __nv_bfloat16 g_vtl[B_ * NH_ * S_ * HD_];

// ---------------------------------------------------------------------------
// fp32 -> bf16 hi/lo split, expanded-K layout (vectorized).
// mode 0 (A side): [hi | lo | hi];  mode 1 (W side): [hi | hi | lo]
// ---------------------------------------------------------------------------
__device__ __forceinline__ void split4(const float* __restrict__ X,
                                       __nv_bfloat16* __restrict__ Y,
                                       int t, int mode)
{
    const int idx = t * 4;
    const int r = idx >> 11;
    const int k = idx & (K_ - 1);
    const float4 x = *(const float4*)(X + idx);

    __nv_bfloat16 hi[4], lo[4];
    const float xs[4] = {x.x, x.y, x.z, x.w};
#pragma unroll
    for (int i = 0; i < 4; i++) {
        hi[i] = __float2bfloat16_rn(xs[i]);
        lo[i] = __float2bfloat16_rn(xs[i] - __bfloat162float(hi[i]));
    }
    __nv_bfloat16* dst = Y + (size_t)r * KEX_ + k;
    *(uint2*)(dst) = *(const uint2*)hi;
    if (mode == 0) {
        *(uint2*)(dst + K_)     = *(const uint2*)lo;
        *(uint2*)(dst + 2 * K_) = *(const uint2*)hi;
    } else {
        *(uint2*)(dst + K_)     = *(const uint2*)hi;
        *(uint2*)(dst + 2 * K_) = *(const uint2*)lo;
    }
}

// Merged: 4 weights (grid.y 0..3, W-mode) + hidden-states A (grid.y 4, A-mode,
// two nW4-sized chunks since nA4 == 2*nW4).
__global__ void split_all(const float* __restrict__ hs,
                          const float* __restrict__ Wq, const float* __restrict__ Wk,
                          const float* __restrict__ Wv, const float* __restrict__ Wo,
                          __nv_bfloat16* __restrict__ Ya,
                          __nv_bfloat16* __restrict__ Yq, __nv_bfloat16* __restrict__ Yk,
                          __nv_bfloat16* __restrict__ Yv, __nv_bfloat16* __restrict__ Yo,
                          int totalW4)
{
    const int t = blockIdx.x * blockDim.x + threadIdx.x;
    if (t >= totalW4) return;
    const int sel = blockIdx.y;
    if (sel == 4) {
        split4(hs, Ya, t, 0);
        split4(hs, Ya, t + totalW4, 0);
        return;
    }
    const float* X = (sel == 0) ? Wq : (sel == 1) ? Wk : (sel == 2) ? Wv : Wo;
    __nv_bfloat16* Y = (sel == 0) ? Yq : (sel == 1) ? Yk : (sel == 2) ? Yv : Yo;
    split4(X, Y, t, 1);
}

// ---------------------------------------------------------------------------
// mma / cp.async helpers
// ---------------------------------------------------------------------------
__device__ __forceinline__ void cpasync16(unsigned int smem_dst, const void* gsrc) {
    asm volatile("cp.async.cg.shared.global [%0], [%1], 16;\n" :: "r"(smem_dst), "l"(gsrc));
}
__device__ __forceinline__ void cp_commit() {
    asm volatile("cp.async.commit_group;\n");
}
__device__ __forceinline__ void ldm_x4(unsigned int& r0, unsigned int& r1,
                                       unsigned int& r2, unsigned int& r3,
                                       unsigned int addr) {
    asm volatile("ldmatrix.sync.aligned.m8n8.x4.shared.b16 {%0,%1,%2,%3}, [%4];\n"
                 : "=r"(r0), "=r"(r1), "=r"(r2), "=r"(r3) : "r"(addr));
}
__device__ __forceinline__ void mma_bf16(float* c, const unsigned int* a,
                                         const unsigned int* b) {
    asm volatile(
        "mma.sync.aligned.m16n8k16.row.col.f32.bf16.bf16.f32 "
        "{%0,%1,%2,%3}, {%4,%5,%6,%7}, {%8,%9}, {%0,%1,%2,%3};\n"
        : "+f"(c[0]), "+f"(c[1]), "+f"(c[2]), "+f"(c[3])
        : "r"(a[0]), "r"(a[1]), "r"(a[2]), "r"(a[3]), "r"(b[0]), "r"(b[1]));
}

__device__ __forceinline__ unsigned int pack_hi2(float a, float b,
                                                 unsigned int& lo_pack) {
    const __nv_bfloat16 h0 = __float2bfloat16_rn(a);
    const __nv_bfloat16 h1 = __float2bfloat16_rn(b);
    const __nv_bfloat16 g0 = __float2bfloat16_rn(a - __bfloat162float(h0));
    const __nv_bfloat16 g1 = __float2bfloat16_rn(b - __bfloat162float(h1));
    lo_pack = ((unsigned int)__bfloat16_as_ushort(g1) << 16) | __bfloat16_as_ushort(g0);
    return ((unsigned int)__bfloat16_as_ushort(h1) << 16) | __bfloat16_as_ushort(h0);
}

// ---------------------------------------------------------------------------
// GEMM configuration (proven R5/R8 shape)
// ---------------------------------------------------------------------------
#define GBM 128
#define GBN 128
#define GBK 64
#define LDP 72
#define GSTG 3
#define STG_B (GBM * LDP * 2)
#define GEMM_SMEM (2 * GSTG * STG_B)

// ---------------------------------------------------------------------------
// Fused QKV GEMM: one launch, grid (48, 32). n-block selects weight + dest.
// Epilogue: paired float2 stores (n, n+1 contiguous within a head).
// ---------------------------------------------------------------------------
__global__ __launch_bounds__(256, 2)
void gemm_qkv(const __nv_bfloat16* __restrict__ A,
              const __nv_bfloat16* __restrict__ Wq,
              const __nv_bfloat16* __restrict__ Wk,
              const __nv_bfloat16* __restrict__ Wv,
              float* __restrict__ Cq, float* __restrict__ Ck,
              float* __restrict__ Cv)
{
    extern __shared__ char gsm[];
    const unsigned int sbase = (unsigned int)__cvta_generic_to_shared(gsm);
    const unsigned int sBoff = GSTG * STG_B;

    const int tid  = threadIdx.x;
    const int lane = tid & 31;
    const int w    = tid >> 5;
    const int wm   = (w >> 1) << 5;
    const int wn   = (w & 1) << 6;
    const int m0   = blockIdx.y * GBM;
    const int ng   = blockIdx.x * GBN;
    const int which = ng >> 11;
    const int n0   = ng & (K_ - 1);

    const __nv_bfloat16* W = (which == 0) ? Wq : (which == 1) ? Wk : Wv;
    float* C = (which == 0) ? Cq : (which == 1) ? Ck : Cv;

    float acc[2][8][4];
#pragma unroll
    for (int mi = 0; mi < 2; mi++)
#pragma unroll
        for (int ni = 0; ni < 8; ni++)
#pragma unroll
            for (int e = 0; e < 4; e++) acc[mi][ni][e] = 0.0f;

    const int lr = tid >> 3;
    const int lc = tid & 7;
    const int NT = KEX_ / GBK;

    auto load_stage = [&](int kt, int s) {
        const unsigned int aD = sbase + s * STG_B;
        const unsigned int bD = sbase + sBoff + s * STG_B;
        const __nv_bfloat16* Ap = A + (size_t)m0 * KEX_ + kt * GBK + lc * 8;
        const __nv_bfloat16* Wp = W + (size_t)n0 * KEX_ + kt * GBK + lc * 8;
#pragma unroll
        for (int i = 0; i < 4; i++) {
            const int row = lr + i * 32;
            const unsigned int off = (unsigned int)(row * LDP + lc * 8) * 2;
            cpasync16(aD + off, Ap + (size_t)row * KEX_);
            cpasync16(bD + off, Wp + (size_t)row * KEX_);
        }
        cp_commit();
    };

    load_stage(0, 0);
    load_stage(1, 1);

    for (int kt = 0; kt < NT; kt++) {
        if (kt + 1 < NT) {
            asm volatile("cp.async.wait_group 1;\n");
        } else {
            asm volatile("cp.async.wait_group 0;\n");
        }
        __syncthreads();

        if (kt + 2 < NT) load_stage(kt + 2, (kt + 2) % GSTG);

        const int s = kt % GSTG;
        const unsigned int aBase = sbase + s * STG_B;
        const unsigned int bBase = sbase + sBoff + s * STG_B;

#pragma unroll
        for (int ks = 0; ks < 4; ks++) {
            unsigned int afr[2][4], bfr[8][2];
#pragma unroll
            for (int mi = 0; mi < 2; mi++) {
                const int row = wm + mi * 16 + (lane & 15);
                const unsigned int addr =
                    aBase + (unsigned int)(row * LDP + ks * 16 + (lane >> 4) * 8) * 2;
                ldm_x4(afr[mi][0], afr[mi][1], afr[mi][2], afr[mi][3], addr);
            }
#pragma unroll
            for (int p = 0; p < 4; p++) {
                const int nrow = wn + p * 16 + (lane & 7) + ((lane >> 4) << 3);
                const int chunk = (lane >> 3) & 1;
                const unsigned int addr =
                    bBase + (unsigned int)(nrow * LDP + ks * 16 + chunk * 8) * 2;
                ldm_x4(bfr[2 * p][0], bfr[2 * p][1], bfr[2 * p + 1][0], bfr[2 * p + 1][1], addr);
            }
#pragma unroll
            for (int mi = 0; mi < 2; mi++)
#pragma unroll
                for (int ni = 0; ni < 8; ni++)
                    mma_bf16(acc[mi][ni], afr[mi], bfr[ni]);
        }
    }

    // epilogue: paired float2 stores (e=0,1 -> n,n+1 ; e=2,3 -> row+8, n,n+1)
#pragma unroll
    for (int mi = 0; mi < 2; mi++) {
#pragma unroll
        for (int ni = 0; ni < 8; ni++) {
            const int rr = m0 + wm + mi * 16 + (lane >> 2);
            const int cc = n0 + wn + ni * 8 + ((lane & 3) << 1);
#pragma unroll
            for (int half = 0; half < 2; half++) {
                const int m = rr + half * 8;
                const int b = m >> 11, s2 = m & (S_ - 1);
                const int h = cc >> 7, d = cc & (HD_ - 1);
                float2 v2;
                v2.x = acc[mi][ni][half * 2];
                v2.y = acc[mi][ni][half * 2 + 1];
                *(float2*)&C[(((size_t)(b * NH_ + h)) * S_ + s2) * HD_ + d] = v2;
            }
        }
    }
}

// ---------------------------------------------------------------------------
// Plain GEMM (Wo projection, layout 0). Paired float2 epilogue stores.
// ---------------------------------------------------------------------------
__global__ __launch_bounds__(256, 2)
void gemm_bf16(const __nv_bfloat16* __restrict__ A,
               const __nv_bfloat16* __restrict__ W,
               float* __restrict__ C, int N, int Kex)
{
    extern __shared__ char gsm[];
    const unsigned int sbase = (unsigned int)__cvta_generic_to_shared(gsm);
    const unsigned int sBoff = GSTG * STG_B;

    const int tid  = threadIdx.x;
    const int lane = tid & 31;
    const int w    = tid >> 5;
    const int wm   = (w >> 1) << 5;
    const int wn   = (w & 1) << 6;
    const int m0   = blockIdx.y * GBM;
    const int n0   = blockIdx.x * GBN;

    float acc[2][8][4];
#pragma unroll
    for (int mi = 0; mi < 2; mi++)
#pragma unroll
        for (int ni = 0; ni < 8; ni++)
#pragma unroll
            for (int e = 0; e < 4; e++) acc[mi][ni][e] = 0.0f;

    const int lr = tid >> 3;
    const int lc = tid & 7;
    const int NT = Kex / GBK;

    auto load_stage = [&](int kt, int s) {
        const unsigned int aD = sbase + s * STG_B;
        const unsigned int bD = sbase + sBoff + s * STG_B;
        const __nv_bfloat16* Ap = A + (size_t)m0 * Kex + kt * GBK + lc * 8;
        const __nv_bfloat16* Wp = W + (size_t)n0 * Kex + kt * GBK + lc * 8;
#pragma unroll
        for (int i = 0; i < 4; i++) {
            const int row = lr + i * 32;
            const unsigned int off = (unsigned int)(row * LDP + lc * 8) * 2;
            cpasync16(aD + off, Ap + (size_t)row * Kex);
            cpasync16(bD + off, Wp + (size_t)row * Kex);
        }
        cp_commit();
    };

    load_stage(0, 0);
    load_stage(1, 1);

    for (int kt = 0; kt < NT; kt++) {
        if (kt + 1 < NT) {
            asm volatile("cp.async.wait_group 1;\n");
        } else {
            asm volatile("cp.async.wait_group 0;\n");
        }
        __syncthreads();

        if (kt + 2 < NT) load_stage(kt + 2, (kt + 2) % GSTG);

        const int s = kt % GSTG;
        const unsigned int aBase = sbase + s * STG_B;
        const unsigned int bBase = sbase + sBoff + s * STG_B;

#pragma unroll
        for (int ks = 0; ks < 4; ks++) {
            unsigned int afr[2][4], bfr[8][2];
#pragma unroll
            for (int mi = 0; mi < 2; mi++) {
                const int row = wm + mi * 16 + (lane & 15);
                const unsigned int addr =
                    aBase + (unsigned int)(row * LDP + ks * 16 + (lane >> 4) * 8) * 2;
                ldm_x4(afr[mi][0], afr[mi][1], afr[mi][2], afr[mi][3], addr);
            }
#pragma unroll
            for (int p = 0; p < 4; p++) {
                const int nrow = wn + p * 16 + (lane & 7) + ((lane >> 4) << 3);
                const int chunk = (lane >> 3) & 1;
                const unsigned int addr =
                    bBase + (unsigned int)(nrow * LDP + ks * 16 + chunk * 8) * 2;
                ldm_x4(bfr[2 * p][0], bfr[2 * p][1], bfr[2 * p + 1][0], bfr[2 * p + 1][1], addr);
            }
#pragma unroll
            for (int mi = 0; mi < 2; mi++)
#pragma unroll
                for (int ni = 0; ni < 8; ni++)
                    mma_bf16(acc[mi][ni], afr[mi], bfr[ni]);
        }
    }

#pragma unroll
    for (int mi = 0; mi < 2; mi++) {
#pragma unroll
        for (int ni = 0; ni < 8; ni++) {
            const int rr = m0 + wm + mi * 16 + (lane >> 2);
            const int cc = n0 + wn + ni * 8 + ((lane & 3) << 1);
#pragma unroll
            for (int half = 0; half < 2; half++) {
                const int m = rr + half * 8;
                float2 v2;
                v2.x = acc[mi][ni][half * 2];
                v2.y = acc[mi][ni][half * 2 + 1];
                *(float2*)&C[(size_t)m * N + cc] = v2;
            }
        }
    }
}

// ---------------------------------------------------------------------------
// RoPE + hi/lo split, pair-vectorized (packed 4B stores).
// ---------------------------------------------------------------------------
__global__ void rope_split(const float* __restrict__ q, const float* __restrict__ k,
                           const int* __restrict__ pos_ids,
                           __nv_bfloat16* __restrict__ qh, __nv_bfloat16* __restrict__ ql,
                           __nv_bfloat16* __restrict__ kh, __nv_bfloat16* __restrict__ kl)
{
    const int idx = blockIdx.x * blockDim.x + threadIdx.x;
    const int total = B_ * NH_ * S_ * 32;   // pairs of d in [0,64)
    if (idx >= total) return;
    const int d = (idx & 31) << 1;
    int t = idx >> 5;
    const int s = t & (S_ - 1);
    t >>= 11;
    const int h = t & (NH_ - 1);
    const int b = t >> 4;

    const int p = pos_ids[b * S_ + s];
    const size_t base = (((size_t)(b * NH_ + h)) * S_ + s) * HD_ + d;

    const float2 q1 = *(const float2*)&q[base];
    const float2 q2 = *(const float2*)&q[base + 64];
    const float2 k1 = *(const float2*)&k[base];
    const float2 k2 = *(const float2*)&k[base + 64];

    float rq1[2], rq2[2], rk1[2], rk2[2];
#pragma unroll
    for (int j = 0; j < 2; j++) {
        const float ee = (float)(-(2 * (d + j))) * 0.10381025296523008f;
        const float ang = (float)p * exp2f(ee);
        float sn, cs;
        sincosf(ang, &sn, &cs);
        const float x1 = j ? q1.y : q1.x, x2 = j ? q2.y : q2.x;
        const float y1 = j ? k1.y : k1.x, y2 = j ? k2.y : k2.x;
        rq1[j] = x1 * cs - x2 * sn;  rq2[j] = x2 * cs + x1 * sn;
        rk1[j] = y1 * cs - y2 * sn;  rk2[j] = y2 * cs + y1 * sn;
    }

    unsigned int lo;
    *(unsigned int*)&qh[base]      = pack_hi2(rq1[0], rq1[1], lo); *(unsigned int*)&ql[base]      = lo;
    *(unsigned int*)&qh[base + 64] = pack_hi2(rq2[0], rq2[1], lo); *(unsigned int*)&ql[base + 64] = lo;
    *(unsigned int*)&kh[base]      = pack_hi2(rk1[0], rk1[1], lo); *(unsigned int*)&kl[base]      = lo;
    *(unsigned int*)&kh[base + 64] = pack_hi2(rk2[0], rk2[1], lo); *(unsigned int*)&kl[base + 64] = lo;
}

// ---------------------------------------------------------------------------
// V transpose + split (packed 4B stores).
// ---------------------------------------------------------------------------
__global__ void vsplit_t(const float* __restrict__ v,
                         __nv_bfloat16* __restrict__ vth,
                         __nv_bfloat16* __restrict__ vtl)
{
    __shared__ float tile[32][33];
    const int bh = blockIdx.z;
    const int s0 = blockIdx.x * 32;
    const int d0 = blockIdx.y * 32;
    const int tx = threadIdx.x;        // 0..31
    const int ty = threadIdx.y;        // 0..7
#pragma unroll
    for (int i = 0; i < 4; i++) {
        const int sr = ty * 4 + i;
        tile[sr][tx] = v[(((size_t)bh * S_) + s0 + sr) * HD_ + d0 + tx];
    }
    __syncthreads();

    const int nt = ty * 32 + tx;
    const int sc2 = nt & 15;           // s-pair index
    const int dr0 = nt >> 4;           // 0..15
#pragma unroll
    for (int i = 0; i < 2; i++) {
        const int dr = dr0 + i * 16;
        const float v0 = tile[2 * sc2][dr];
        const float v1 = tile[2 * sc2 + 1][dr];
        unsigned int lo;
        const unsigned int hi = pack_hi2(v0, v1, lo);
        const size_t o = (((size_t)bh * HD_) + d0 + dr) * S_ + s0 + 2 * sc2;
        *(unsigned int*)&vth[o] = hi;
        *(unsigned int*)&vtl[o] = lo;
    }
}

// ---------------------------------------------------------------------------
// Flash attention on tensor cores (bf16 hi/lo 3-term splits, fp32 softmax).
// 64 q-rows per CTA, 4 warps, 64-kv tiles, HD=128. LPT scheduling.
// Epilogue writes cex (hi|lo|hi expanded) directly with packed 4B stores.
// ---------------------------------------------------------------------------
#define FS_QH 0
#define FS_QL 17408
#define FS_KH 34816
#define FS_KL 52224
#define FS_VH 69632
#define FS_VL 88064
#define FSMEM_TOTAL 106496

__global__ __launch_bounds__(128, 2)
void flash_mma(const __nv_bfloat16* __restrict__ qh_g, const __nv_bfloat16* __restrict__ ql_g,
               const __nv_bfloat16* __restrict__ kh_g, const __nv_bfloat16* __restrict__ kl_g,
               const __nv_bfloat16* __restrict__ vth_g, const __nv_bfloat16* __restrict__ vtl_g,
               __nv_bfloat16* __restrict__ cex)
{
    extern __shared__ char fsm[];
    const unsigned int sb = (unsigned int)__cvta_generic_to_shared(fsm);
    const int tid  = threadIdx.x;
    const int lane = tid & 31;
    const int w    = tid >> 5;
    const int qt   = (S_ / 64 - 1) - blockIdx.x;   // longest-first (LPT)
    const int bh   = blockIdx.y;

    // preload Q tiles (hi + lo)
    {
        const size_t qoff = (((size_t)bh * S_) + qt * 64) * HD_;
#pragma unroll
        for (int i = 0; i < 8; i++) {
            const int idx = tid + i * 128;
            const int row = idx >> 4, c = idx & 15;
            const unsigned int off = (unsigned int)(row * 136 + c * 8) * 2;
            cpasync16(sb + FS_QH + off, qh_g + qoff + (size_t)row * HD_ + c * 8);
            cpasync16(sb + FS_QL + off, ql_g + qoff + (size_t)row * HD_ + c * 8);
        }
        cp_commit();
    }

    float oacc[16][4];
#pragma unroll
    for (int ni = 0; ni < 16; ni++)
#pragma unroll
        for (int e = 0; e < 4; e++) oacc[ni][e] = 0.0f;
    float m_i[2] = {-3.0e30f, -3.0e30f};
    float l_i[2] = {0.0f, 0.0f};

    const float SCALE = 0.08838834764831845f;   // 1/sqrt(128)

    for (int j = 0; j <= qt; j++) {
        {
            const size_t koff = (((size_t)bh * S_) + j * 64) * HD_;
            const size_t voff = ((size_t)bh * HD_) * S_ + j * 64;
#pragma unroll
            for (int i = 0; i < 8; i++) {
                const int idx = tid + i * 128;
                const int r16 = idx >> 4, c16 = idx & 15;
                const unsigned int offk = (unsigned int)(r16 * 136 + c16 * 8) * 2;
                cpasync16(sb + FS_KH + offk, kh_g + koff + (size_t)r16 * HD_ + c16 * 8);
                cpasync16(sb + FS_KL + offk, kl_g + koff + (size_t)r16 * HD_ + c16 * 8);
                const int r8 = idx >> 3, c8 = idx & 7;
                const unsigned int offv = (unsigned int)(r8 * 72 + c8 * 8) * 2;
                cpasync16(sb + FS_VH + offv, vth_g + voff + (size_t)r8 * S_ + c8 * 8);
                cpasync16(sb + FS_VL + offv, vtl_g + voff + (size_t)r8 * S_ + c8 * 8);
            }
            cp_commit();
        }
        asm volatile("cp.async.wait_group 0;\n");
        __syncthreads();

        // ---- scores: S = Qh·Kh^T + Ql·Kh^T + Qh·Kl^T ----
        float sreg[8][4];
#pragma unroll
        for (int ni = 0; ni < 8; ni++)
#pragma unroll
            for (int e = 0; e < 4; e++) sreg[ni][e] = 0.0f;

#pragma unroll
        for (int kt = 0; kt < 8; kt++) {
            unsigned int qfh[4], qfl[4], bfh[8][2], bfl[8][2];
            const int arow = w * 16 + (lane & 15);
            const unsigned int aoff = (unsigned int)(arow * 136 + kt * 16 + (lane >> 4) * 8) * 2;
            ldm_x4(qfh[0], qfh[1], qfh[2], qfh[3], sb + FS_QH + aoff);
            ldm_x4(qfl[0], qfl[1], qfl[2], qfl[3], sb + FS_QL + aoff);
#pragma unroll
            for (int p = 0; p < 4; p++) {
                const int nrow = p * 16 + (lane & 7) + ((lane >> 4) << 3);
                const unsigned int boff =
                    (unsigned int)(nrow * 136 + kt * 16 + ((lane >> 3) & 1) * 8) * 2;
                ldm_x4(bfh[2*p][0], bfh[2*p][1], bfh[2*p+1][0], bfh[2*p+1][1], sb + FS_KH + boff);
                ldm_x4(bfl[2*p][0], bfl[2*p][1], bfl[2*p+1][0], bfl[2*p+1][1], sb + FS_KL + boff);
            }
#pragma unroll
            for (int ni = 0; ni < 8; ni++) mma_bf16(sreg[ni], qfh, bfh[ni]);
#pragma unroll
            for (int ni = 0; ni < 8; ni++) mma_bf16(sreg[ni], qfl, bfh[ni]);
#pragma unroll
            for (int ni = 0; ni < 8; ni++) mma_bf16(sreg[ni], qfh, bfl[ni]);
        }

        // ---- scale + causal mask ----
        const bool diag = (j == qt);
        const int r0 = lane >> 2;
        const int c0 = (lane & 3) << 1;
#pragma unroll
        for (int ni = 0; ni < 8; ni++)
#pragma unroll
            for (int e = 0; e < 4; e++) {
                sreg[ni][e] *= SCALE;
                if (diag) {
                    const int qrow = w * 16 + r0 + ((e >> 1) << 3);
                    const int kcol = ni * 8 + c0 + (e & 1);
                    if (kcol > qrow) sreg[ni][e] = -1.0e30f;
                }
            }

        // ---- online softmax ----
        float corr[2];
#pragma unroll
        for (int h2 = 0; h2 < 2; h2++) {
            const int e0 = h2 * 2;
            float mloc = -3.0e30f;
#pragma unroll
            for (int ni = 0; ni < 8; ni++)
                mloc = fmaxf(mloc, fmaxf(sreg[ni][e0], sreg[ni][e0 + 1]));
            mloc = fmaxf(mloc, __shfl_xor_sync(0xffffffffu, mloc, 1));
            mloc = fmaxf(mloc, __shfl_xor_sync(0xffffffffu, mloc, 2));
            const float mnew = fmaxf(m_i[h2], mloc);
            corr[h2] = __expf(m_i[h2] - mnew);
            m_i[h2] = mnew;
            float lloc = 0.0f;
#pragma unroll
            for (int ni = 0; ni < 8; ni++) {
                const float p0 = __expf(sreg[ni][e0]     - mnew);
                const float p1 = __expf(sreg[ni][e0 + 1] - mnew);
                sreg[ni][e0] = p0; sreg[ni][e0 + 1] = p1;
                lloc += p0 + p1;
            }
            lloc += __shfl_xor_sync(0xffffffffu, lloc, 1);
            lloc += __shfl_xor_sync(0xffffffffu, lloc, 2);
            l_i[h2] = l_i[h2] * corr[h2] + lloc;
        }
#pragma unroll
        for (int ni = 0; ni < 16; ni++)
#pragma unroll
            for (int e = 0; e < 4; e++) oacc[ni][e] *= corr[e >> 1];

        // ---- repack P into A-fragments (hi/lo) ----
        unsigned int pah[4][4], pal[4][4];
#pragma unroll
        for (int t = 0; t < 4; t++) {
#pragma unroll
            for (int rix = 0; rix < 4; rix++) {
                const int ni = 2 * t + (rix >> 1);
                const int eb = (rix & 1) * 2;
                pah[t][rix] = pack_hi2(sreg[ni][eb], sreg[ni][eb + 1], pal[t][rix]);
            }
        }

        // ---- O += Ph·Vh + Pl·Vh + Ph·Vl ----
#pragma unroll
        for (int t = 0; t < 4; t++) {
            unsigned int bvh[16][2], bvl[16][2];
#pragma unroll
            for (int p = 0; p < 8; p++) {
                const int nrow = p * 16 + (lane & 7) + ((lane >> 4) << 3);
                const unsigned int boff =
                    (unsigned int)(nrow * 72 + t * 16 + ((lane >> 3) & 1) * 8) * 2;
                ldm_x4(bvh[2*p][0], bvh[2*p][1], bvh[2*p+1][0], bvh[2*p+1][1], sb + FS_VH + boff);
                ldm_x4(bvl[2*p][0], bvl[2*p][1], bvl[2*p+1][0], bvl[2*p+1][1], sb + FS_VL + boff);
            }
#pragma unroll
            for (int ni = 0; ni < 16; ni++) mma_bf16(oacc[ni], pah[t], bvh[ni]);
#pragma unroll
            for (int ni = 0; ni < 16; ni++) mma_bf16(oacc[ni], pal[t], bvh[ni]);
#pragma unroll
            for (int ni = 0; ni < 16; ni++) mma_bf16(oacc[ni], pah[t], bvl[ni]);
        }
        __syncthreads();   // before next j overwrites K/V smem
    }

    // ---- epilogue: write cex (hi|lo|hi) directly, packed 4B stores ----
    const float linv[2] = {1.0f / l_i[0], 1.0f / l_i[1]};
    const int b = bh >> 4;
    const int h = bh & (NH_ - 1);
    const int d0base = (lane & 3) << 1;
#pragma unroll
    for (int ni = 0; ni < 16; ni++) {
#pragma unroll
        for (int half = 0; half < 2; half++) {
            const int e0 = half * 2;
            const int qrow = qt * 64 + w * 16 + (lane >> 2) + half * 8;
            const int d0 = ni * 8 + d0base;
            const float v0 = oacc[ni][e0]     * linv[half];
            const float v1 = oacc[ni][e0 + 1] * linv[half];
            unsigned int lo;
            const unsigned int hi = pack_hi2(v0, v1, lo);
            __nv_bfloat16* dst =
                cex + ((size_t)b * S_ + qrow) * KEX_ + h * HD_ + d0;
            *(unsigned int*)(dst)          = hi;
            *(unsigned int*)(dst + K_)     = lo;
            *(unsigned int*)(dst + 2 * K_) = hi;
        }
    }
}

// ---------------------------------------------------------------------------
extern "C" void kernel_launch(void* const* d_in, const int* in_sizes, int n_in,
                              void* d_out, int out_size)
{
    const float* hs  = (const float*)d_in[0];
    // d_in[1] = attention_mask: deterministically causal, applied analytically
    const int*   pos = (const int*)d_in[2];
    const float* Wq  = (const float*)d_in[3];
    const float* Wk  = (const float*)d_in[4];
    const float* Wv  = (const float*)d_in[5];
    const float* Wo  = (const float*)d_in[6];
    float* out = (float*)d_out;

    float *q, *k, *v;
    __nv_bfloat16 *aex, *cex, *wqe, *wke, *wve, *woe;
    __nv_bfloat16 *qh, *ql, *kh, *kl, *vth, *vtl;
    cudaGetSymbolAddress((void**)&q,   g_q);
    cudaGetSymbolAddress((void**)&k,   g_k);
    cudaGetSymbolAddress((void**)&v,   g_v);
    cudaGetSymbolAddress((void**)&aex, g_aex);
    cudaGetSymbolAddress((void**)&cex, g_cex);
    cudaGetSymbolAddress((void**)&wqe, g_wqe);
    cudaGetSymbolAddress((void**)&wke, g_wke);
    cudaGetSymbolAddress((void**)&wve, g_wve);
    cudaGetSymbolAddress((void**)&woe, g_woe);
    cudaGetSymbolAddress((void**)&qh,  g_qh);
    cudaGetSymbolAddress((void**)&ql,  g_ql);
    cudaGetSymbolAddress((void**)&kh,  g_kh);
    cudaGetSymbolAddress((void**)&kl,  g_kl);
    cudaGetSymbolAddress((void**)&vth, g_vth);
    cudaGetSymbolAddress((void**)&vtl, g_vtl);

    const int nW4 = (HID_ * K_) / 4;
    // one launch: 4 weights + hidden states
    split_all<<<dim3((nW4 + 255) / 256, 5), 256>>>(hs, Wq, Wk, Wv, Wo,
                                                   aex, wqe, wke, wve, woe, nW4);

    static bool attr_set = false;
    if (!attr_set) {
        cudaFuncSetAttribute(gemm_qkv,  cudaFuncAttributeMaxDynamicSharedMemorySize, GEMM_SMEM);
        cudaFuncSetAttribute(gemm_bf16, cudaFuncAttributeMaxDynamicSharedMemorySize, GEMM_SMEM);
        cudaFuncSetAttribute(flash_mma, cudaFuncAttributeMaxDynamicSharedMemorySize, FSMEM_TOTAL);
        attr_set = true;
    }

    // fused QKV projection: one launch, grid (48, 32)
    gemm_qkv<<<dim3(3 * HID_ / GBN, M_ / GBM), 256, GEMM_SMEM>>>(
        aex, wqe, wke, wve, q, k, v);

    const int rope_total = B_ * NH_ * S_ * 32;
    rope_split<<<(rope_total + 255) / 256, 256>>>(q, k, pos, qh, ql, kh, kl);

    vsplit_t<<<dim3(S_ / 32, HD_ / 32, B_ * NH_), dim3(32, 8)>>>(v, vth, vtl);

    // flash attention writes cex (expanded) directly
    flash_mma<<<dim3(S_ / 64, B_ * NH_), 128, FSMEM_TOTAL>>>(qh, ql, kh, kl, vth, vtl, cex);

    gemm_bf16<<<dim3(HID_ / GBN, M_ / GBM), 256, GEMM_SMEM>>>(cex, woe, out, HID_, KEX_);
}

// round 17
// speedup vs baseline: 1.0106x; 1.0017x over previous
#include <cuda_runtime.h>
#include <cuda_bf16.h>
#include <cstdint>
#include <cstddef>
#include <math.h>

// Problem constants
#define B_   2
#define S_   2048
#define HID_ 2048
#define NH_  16
#define HD_  128
#define M_   (B_ * S_)     // 4096
#define K_   HID_          // 2048
#define KEX_ (3 * K_)      // 6144 expanded (hi|lo|hi split)

// ---------------------------------------------------------------------------
// Scratch (allocation-free rule: __device__ globals)
// ---------------------------------------------------------------------------
__device__ float g_q[B_ * NH_ * S_ * HD_];     // [b,h,s,d] fp32
__device__ float g_k[B_ * NH_ * S_ * HD_];
__device__ float g_v[B_ * NH_ * S_ * HD_];

__device__ __nv_bfloat16 g_aex[(size_t)M_ * KEX_];
__device__ __nv_bfloat16 g_cex[(size_t)M_ * KEX_];
__device__ __nv_bfloat16 g_wqe[(size_t)HID_ * KEX_];
__device__ __nv_bfloat16 g_wke[(size_t)HID_ * KEX_];
__device__ __nv_bfloat16 g_wve[(size_t)HID_ * KEX_];
__device__ __nv_bfloat16 g_woe[(size_t)HID_ * KEX_];

// flash operands: hi/lo bf16
__device__ __nv_bfloat16 g_qh[B_ * NH_ * S_ * HD_];   // [b,h,s,d]
__device__ __nv_bfloat16 g_ql[B_ * NH_ * S_ * HD_];
__device__ __nv_bfloat16 g_kh[B_ * NH_ * S_ * HD_];
__device__ __nv_bfloat16 g_kl[B_ * NH_ * S_ * HD_];
__device__ __nv_bfloat16 g_vth[B_ * NH_ * S_ * HD_];  // [b,h,d,s] (transposed)
__device__ __nv_bfloat16 g_vtl[B_ * NH_ * S_ * HD_];

// ---------------------------------------------------------------------------
// pack helpers
// ---------------------------------------------------------------------------
__device__ __forceinline__ unsigned int pack_hi2(float a, float b,
                                                 unsigned int& lo_pack) {
    const __nv_bfloat16 h0 = __float2bfloat16_rn(a);
    const __nv_bfloat16 h1 = __float2bfloat16_rn(b);
    const __nv_bfloat16 g0 = __float2bfloat16_rn(a - __bfloat162float(h0));
    const __nv_bfloat16 g1 = __float2bfloat16_rn(b - __bfloat162float(h1));
    lo_pack = ((unsigned int)__bfloat16_as_ushort(g1) << 16) | __bfloat16_as_ushort(g0);
    return ((unsigned int)__bfloat16_as_ushort(h1) << 16) | __bfloat16_as_ushort(h0);
}

// ---------------------------------------------------------------------------
// fp32 -> bf16 hi/lo split, expanded-K layout, 8 elems/thread (16B stores).
// mode 0 (A side): [hi | lo | hi];  mode 1 (W side): [hi | hi | lo]
// ---------------------------------------------------------------------------
__device__ __forceinline__ void split8(const float* __restrict__ X,
                                       __nv_bfloat16* __restrict__ Y,
                                       int t, int mode)
{
    const int idx = t * 8;
    const int r = idx >> 11;
    const int k = idx & (K_ - 1);
    const float4 x0 = *(const float4*)(X + idx);
    const float4 x1 = *(const float4*)(X + idx + 4);

    const float xs[8] = {x0.x, x0.y, x0.z, x0.w, x1.x, x1.y, x1.z, x1.w};
    unsigned int hiw[4], low[4];
#pragma unroll
    for (int i = 0; i < 4; i++)
        hiw[i] = pack_hi2(xs[2 * i], xs[2 * i + 1], low[i]);

    __nv_bfloat16* dst = Y + (size_t)r * KEX_ + k;
    *(uint4*)(dst) = *(const uint4*)hiw;
    if (mode == 0) {
        *(uint4*)(dst + K_)     = *(const uint4*)low;
        *(uint4*)(dst + 2 * K_) = *(const uint4*)hiw;
    } else {
        *(uint4*)(dst + K_)     = *(const uint4*)hiw;
        *(uint4*)(dst + 2 * K_) = *(const uint4*)low;
    }
}

// Merged: 4 weights (grid.y 0..3, W-mode) + hidden-states A (grid.y 4, A-mode,
// two totalW8-sized chunks since nA8 == 2*nW8).
__global__ void split_all(const float* __restrict__ hs,
                          const float* __restrict__ Wq, const float* __restrict__ Wk,
                          const float* __restrict__ Wv, const float* __restrict__ Wo,
                          __nv_bfloat16* __restrict__ Ya,
                          __nv_bfloat16* __restrict__ Yq, __nv_bfloat16* __restrict__ Yk,
                          __nv_bfloat16* __restrict__ Yv, __nv_bfloat16* __restrict__ Yo,
                          int totalW8)
{
    const int t = blockIdx.x * blockDim.x + threadIdx.x;
    if (t >= totalW8) return;
    const int sel = blockIdx.y;
    if (sel == 4) {
        split8(hs, Ya, t, 0);
        split8(hs, Ya, t + totalW8, 0);
        return;
    }
    const float* X = (sel == 0) ? Wq : (sel == 1) ? Wk : (sel == 2) ? Wv : Wo;
    __nv_bfloat16* Y = (sel == 0) ? Yq : (sel == 1) ? Yk : (sel == 2) ? Yv : Yo;
    split8(X, Y, t, 1);
}

// ---------------------------------------------------------------------------
// mma / cp.async helpers
// ---------------------------------------------------------------------------
__device__ __forceinline__ void cpasync16(unsigned int smem_dst, const void* gsrc) {
    asm volatile("cp.async.cg.shared.global [%0], [%1], 16;\n" :: "r"(smem_dst), "l"(gsrc));
}
__device__ __forceinline__ void cp_commit() {
    asm volatile("cp.async.commit_group;\n");
}
__device__ __forceinline__ void ldm_x4(unsigned int& r0, unsigned int& r1,
                                       unsigned int& r2, unsigned int& r3,
                                       unsigned int addr) {
    asm volatile("ldmatrix.sync.aligned.m8n8.x4.shared.b16 {%0,%1,%2,%3}, [%4];\n"
                 : "=r"(r0), "=r"(r1), "=r"(r2), "=r"(r3) : "r"(addr));
}
__device__ __forceinline__ void mma_bf16(float* c, const unsigned int* a,
                                         const unsigned int* b) {
    asm volatile(
        "mma.sync.aligned.m16n8k16.row.col.f32.bf16.bf16.f32 "
        "{%0,%1,%2,%3}, {%4,%5,%6,%7}, {%8,%9}, {%0,%1,%2,%3};\n"
        : "+f"(c[0]), "+f"(c[1]), "+f"(c[2]), "+f"(c[3])
        : "r"(a[0]), "r"(a[1]), "r"(a[2]), "r"(a[3]), "r"(b[0]), "r"(b[1]));
}

// ---------------------------------------------------------------------------
// GEMM configuration (proven R5/R8 shape)
// ---------------------------------------------------------------------------
#define GBM 128
#define GBN 128
#define GBK 64
#define LDP 72
#define GSTG 3
#define STG_B (GBM * LDP * 2)
#define GEMM_SMEM (2 * GSTG * STG_B)

// ---------------------------------------------------------------------------
// Fused QKV GEMM: one launch, grid (48, 32). n-block selects weight + dest.
// Epilogue: paired float2 stores.
// ---------------------------------------------------------------------------
__global__ __launch_bounds__(256, 2)
void gemm_qkv(const __nv_bfloat16* __restrict__ A,
              const __nv_bfloat16* __restrict__ Wq,
              const __nv_bfloat16* __restrict__ Wk,
              const __nv_bfloat16* __restrict__ Wv,
              float* __restrict__ Cq, float* __restrict__ Ck,
              float* __restrict__ Cv)
{
    extern __shared__ char gsm[];
    const unsigned int sbase = (unsigned int)__cvta_generic_to_shared(gsm);
    const unsigned int sBoff = GSTG * STG_B;

    const int tid  = threadIdx.x;
    const int lane = tid & 31;
    const int w    = tid >> 5;
    const int wm   = (w >> 1) << 5;
    const int wn   = (w & 1) << 6;
    const int m0   = blockIdx.y * GBM;
    const int ng   = blockIdx.x * GBN;
    const int which = ng >> 11;
    const int n0   = ng & (K_ - 1);

    const __nv_bfloat16* W = (which == 0) ? Wq : (which == 1) ? Wk : Wv;
    float* C = (which == 0) ? Cq : (which == 1) ? Ck : Cv;

    float acc[2][8][4];
#pragma unroll
    for (int mi = 0; mi < 2; mi++)
#pragma unroll
        for (int ni = 0; ni < 8; ni++)
#pragma unroll
            for (int e = 0; e < 4; e++) acc[mi][ni][e] = 0.0f;

    const int lr = tid >> 3;
    const int lc = tid & 7;
    const int NT = KEX_ / GBK;

    auto load_stage = [&](int kt, int s) {
        const unsigned int aD = sbase + s * STG_B;
        const unsigned int bD = sbase + sBoff + s * STG_B;
        const __nv_bfloat16* Ap = A + (size_t)m0 * KEX_ + kt * GBK + lc * 8;
        const __nv_bfloat16* Wp = W + (size_t)n0 * KEX_ + kt * GBK + lc * 8;
#pragma unroll
        for (int i = 0; i < 4; i++) {
            const int row = lr + i * 32;
            const unsigned int off = (unsigned int)(row * LDP + lc * 8) * 2;
            cpasync16(aD + off, Ap + (size_t)row * KEX_);
            cpasync16(bD + off, Wp + (size_t)row * KEX_);
        }
        cp_commit();
    };

    load_stage(0, 0);
    load_stage(1, 1);

    for (int kt = 0; kt < NT; kt++) {
        if (kt + 1 < NT) {
            asm volatile("cp.async.wait_group 1;\n");
        } else {
            asm volatile("cp.async.wait_group 0;\n");
        }
        __syncthreads();

        if (kt + 2 < NT) load_stage(kt + 2, (kt + 2) % GSTG);

        const int s = kt % GSTG;
        const unsigned int aBase = sbase + s * STG_B;
        const unsigned int bBase = sbase + sBoff + s * STG_B;

#pragma unroll
        for (int ks = 0; ks < 4; ks++) {
            unsigned int afr[2][4], bfr[8][2];
#pragma unroll
            for (int mi = 0; mi < 2; mi++) {
                const int row = wm + mi * 16 + (lane & 15);
                const unsigned int addr =
                    aBase + (unsigned int)(row * LDP + ks * 16 + (lane >> 4) * 8) * 2;
                ldm_x4(afr[mi][0], afr[mi][1], afr[mi][2], afr[mi][3], addr);
            }
#pragma unroll
            for (int p = 0; p < 4; p++) {
                const int nrow = wn + p * 16 + (lane & 7) + ((lane >> 4) << 3);
                const int chunk = (lane >> 3) & 1;
                const unsigned int addr =
                    bBase + (unsigned int)(nrow * LDP + ks * 16 + chunk * 8) * 2;
                ldm_x4(bfr[2 * p][0], bfr[2 * p][1], bfr[2 * p + 1][0], bfr[2 * p + 1][1], addr);
            }
#pragma unroll
            for (int mi = 0; mi < 2; mi++)
#pragma unroll
                for (int ni = 0; ni < 8; ni++)
                    mma_bf16(acc[mi][ni], afr[mi], bfr[ni]);
        }
    }

#pragma unroll
    for (int mi = 0; mi < 2; mi++) {
#pragma unroll
        for (int ni = 0; ni < 8; ni++) {
            const int rr = m0 + wm + mi * 16 + (lane >> 2);
            const int cc = n0 + wn + ni * 8 + ((lane & 3) << 1);
#pragma unroll
            for (int half = 0; half < 2; half++) {
                const int m = rr + half * 8;
                const int b = m >> 11, s2 = m & (S_ - 1);
                const int h = cc >> 7, d = cc & (HD_ - 1);
                float2 v2;
                v2.x = acc[mi][ni][half * 2];
                v2.y = acc[mi][ni][half * 2 + 1];
                *(float2*)&C[(((size_t)(b * NH_ + h)) * S_ + s2) * HD_ + d] = v2;
            }
        }
    }
}

// ---------------------------------------------------------------------------
// Plain GEMM (Wo projection, layout 0). Paired float2 epilogue stores.
// ---------------------------------------------------------------------------
__global__ __launch_bounds__(256, 2)
void gemm_bf16(const __nv_bfloat16* __restrict__ A,
               const __nv_bfloat16* __restrict__ W,
               float* __restrict__ C, int N, int Kex)
{
    extern __shared__ char gsm[];
    const unsigned int sbase = (unsigned int)__cvta_generic_to_shared(gsm);
    const unsigned int sBoff = GSTG * STG_B;

    const int tid  = threadIdx.x;
    const int lane = tid & 31;
    const int w    = tid >> 5;
    const int wm   = (w >> 1) << 5;
    const int wn   = (w & 1) << 6;
    const int m0   = blockIdx.y * GBM;
    const int n0   = blockIdx.x * GBN;

    float acc[2][8][4];
#pragma unroll
    for (int mi = 0; mi < 2; mi++)
#pragma unroll
        for (int ni = 0; ni < 8; ni++)
#pragma unroll
            for (int e = 0; e < 4; e++) acc[mi][ni][e] = 0.0f;

    const int lr = tid >> 3;
    const int lc = tid & 7;
    const int NT = Kex / GBK;

    auto load_stage = [&](int kt, int s) {
        const unsigned int aD = sbase + s * STG_B;
        const unsigned int bD = sbase + sBoff + s * STG_B;
        const __nv_bfloat16* Ap = A + (size_t)m0 * Kex + kt * GBK + lc * 8;
        const __nv_bfloat16* Wp = W + (size_t)n0 * Kex + kt * GBK + lc * 8;
#pragma unroll
        for (int i = 0; i < 4; i++) {
            const int row = lr + i * 32;
            const unsigned int off = (unsigned int)(row * LDP + lc * 8) * 2;
            cpasync16(aD + off, Ap + (size_t)row * Kex);
            cpasync16(bD + off, Wp + (size_t)row * Kex);
        }
        cp_commit();
    };

    load_stage(0, 0);
    load_stage(1, 1);

    for (int kt = 0; kt < NT; kt++) {
        if (kt + 1 < NT) {
            asm volatile("cp.async.wait_group 1;\n");
        } else {
            asm volatile("cp.async.wait_group 0;\n");
        }
        __syncthreads();

        if (kt + 2 < NT) load_stage(kt + 2, (kt + 2) % GSTG);

        const int s = kt % GSTG;
        const unsigned int aBase = sbase + s * STG_B;
        const unsigned int bBase = sbase + sBoff + s * STG_B;

#pragma unroll
        for (int ks = 0; ks < 4; ks++) {
            unsigned int afr[2][4], bfr[8][2];
#pragma unroll
            for (int mi = 0; mi < 2; mi++) {
                const int row = wm + mi * 16 + (lane & 15);
                const unsigned int addr =
                    aBase + (unsigned int)(row * LDP + ks * 16 + (lane >> 4) * 8) * 2;
                ldm_x4(afr[mi][0], afr[mi][1], afr[mi][2], afr[mi][3], addr);
            }
#pragma unroll
            for (int p = 0; p < 4; p++) {
                const int nrow = wn + p * 16 + (lane & 7) + ((lane >> 4) << 3);
                const int chunk = (lane >> 3) & 1;
                const unsigned int addr =
                    bBase + (unsigned int)(nrow * LDP + ks * 16 + chunk * 8) * 2;
                ldm_x4(bfr[2 * p][0], bfr[2 * p][1], bfr[2 * p + 1][0], bfr[2 * p + 1][1], addr);
            }
#pragma unroll
            for (int mi = 0; mi < 2; mi++)
#pragma unroll
                for (int ni = 0; ni < 8; ni++)
                    mma_bf16(acc[mi][ni], afr[mi], bfr[ni]);
        }
    }

#pragma unroll
    for (int mi = 0; mi < 2; mi++) {
#pragma unroll
        for (int ni = 0; ni < 8; ni++) {
            const int rr = m0 + wm + mi * 16 + (lane >> 2);
            const int cc = n0 + wn + ni * 8 + ((lane & 3) << 1);
#pragma unroll
            for (int half = 0; half < 2; half++) {
                const int m = rr + half * 8;
                float2 v2;
                v2.x = acc[mi][ni][half * 2];
                v2.y = acc[mi][ni][half * 2 + 1];
                *(float2*)&C[(size_t)m * N + cc] = v2;
            }
        }
    }
}

// ---------------------------------------------------------------------------
// RoPE + hi/lo split, quad-vectorized: thread handles d..d+3 (and +64 halves).
// 8B uint2 stores (4 bf16 each).
// ---------------------------------------------------------------------------
__global__ void rope_split(const float* __restrict__ q, const float* __restrict__ k,
                           const int* __restrict__ pos_ids,
                           __nv_bfloat16* __restrict__ qh, __nv_bfloat16* __restrict__ ql,
                           __nv_bfloat16* __restrict__ kh, __nv_bfloat16* __restrict__ kl)
{
    const int idx = blockIdx.x * blockDim.x + threadIdx.x;
    const int total = B_ * NH_ * S_ * 16;   // d-quads in [0,64)
    if (idx >= total) return;
    const int d = (idx & 15) << 2;
    int t = idx >> 4;
    const int s = t & (S_ - 1);
    t >>= 11;
    const int h = t & (NH_ - 1);
    const int b = t >> 4;

    const int p = pos_ids[b * S_ + s];
    const size_t base = (((size_t)(b * NH_ + h)) * S_ + s) * HD_ + d;

    const float4 q1 = *(const float4*)&q[base];
    const float4 q2 = *(const float4*)&q[base + 64];
    const float4 k1 = *(const float4*)&k[base];
    const float4 k2 = *(const float4*)&k[base + 64];
    const float q1s[4] = {q1.x, q1.y, q1.z, q1.w};
    const float q2s[4] = {q2.x, q2.y, q2.z, q2.w};
    const float k1s[4] = {k1.x, k1.y, k1.z, k1.w};
    const float k2s[4] = {k2.x, k2.y, k2.z, k2.w};

    float rq1[4], rq2[4], rk1[4], rk2[4];
#pragma unroll
    for (int j = 0; j < 4; j++) {
        const float ee = (float)(-(2 * (d + j))) * 0.10381025296523008f;
        const float ang = (float)p * exp2f(ee);
        float sn, cs;
        sincosf(ang, &sn, &cs);
        rq1[j] = q1s[j] * cs - q2s[j] * sn;  rq2[j] = q2s[j] * cs + q1s[j] * sn;
        rk1[j] = k1s[j] * cs - k2s[j] * sn;  rk2[j] = k2s[j] * cs + k1s[j] * sn;
    }

    uint2 hw, lw;
    hw.x = pack_hi2(rq1[0], rq1[1], lw.x); hw.y = pack_hi2(rq1[2], rq1[3], lw.y);
    *(uint2*)&qh[base] = hw;      *(uint2*)&ql[base] = lw;
    hw.x = pack_hi2(rq2[0], rq2[1], lw.x); hw.y = pack_hi2(rq2[2], rq2[3], lw.y);
    *(uint2*)&qh[base + 64] = hw; *(uint2*)&ql[base + 64] = lw;
    hw.x = pack_hi2(rk1[0], rk1[1], lw.x); hw.y = pack_hi2(rk1[2], rk1[3], lw.y);
    *(uint2*)&kh[base] = hw;      *(uint2*)&kl[base] = lw;
    hw.x = pack_hi2(rk2[0], rk2[1], lw.x); hw.y = pack_hi2(rk2[2], rk2[3], lw.y);
    *(uint2*)&kh[base + 64] = hw; *(uint2*)&kl[base + 64] = lw;
}

// ---------------------------------------------------------------------------
// V transpose + split: s-quads, 8B uint2 stores. One item per thread.
// ---------------------------------------------------------------------------
__global__ void vsplit_t(const float* __restrict__ v,
                         __nv_bfloat16* __restrict__ vth,
                         __nv_bfloat16* __restrict__ vtl)
{
    __shared__ float tile[32][33];
    const int bh = blockIdx.z;
    const int s0 = blockIdx.x * 32;
    const int d0 = blockIdx.y * 32;
    const int tx = threadIdx.x;        // 0..31
    const int ty = threadIdx.y;        // 0..7
#pragma unroll
    for (int i = 0; i < 4; i++) {
        const int sr = ty * 4 + i;
        tile[sr][tx] = v[(((size_t)bh * S_) + s0 + sr) * HD_ + d0 + tx];
    }
    __syncthreads();

    const int nt = ty * 32 + tx;       // 0..255
    const int sq = nt & 7;             // s-quad index (0..7)
    const int dr = nt >> 3;            // d-row (0..31)
    const float v0 = tile[4 * sq + 0][dr];
    const float v1 = tile[4 * sq + 1][dr];
    const float v2 = tile[4 * sq + 2][dr];
    const float v3 = tile[4 * sq + 3][dr];
    uint2 hw, lw;
    hw.x = pack_hi2(v0, v1, lw.x);
    hw.y = pack_hi2(v2, v3, lw.y);
    const size_t o = (((size_t)bh * HD_) + d0 + dr) * S_ + s0 + 4 * sq;
    *(uint2*)&vth[o] = hw;
    *(uint2*)&vtl[o] = lw;
}

// ---------------------------------------------------------------------------
// Flash attention on tensor cores (bf16 hi/lo 3-term splits, fp32 softmax).
// 64 q-rows per CTA, 4 warps, 64-kv tiles, HD=128. LPT scheduling.
// Epilogue writes cex (hi|lo|hi expanded) directly with packed 4B stores.
// ---------------------------------------------------------------------------
#define FS_QH 0
#define FS_QL 17408
#define FS_KH 34816
#define FS_KL 52224
#define FS_VH 69632
#define FS_VL 88064
#define FSMEM_TOTAL 106496

__global__ __launch_bounds__(128, 2)
void flash_mma(const __nv_bfloat16* __restrict__ qh_g, const __nv_bfloat16* __restrict__ ql_g,
               const __nv_bfloat16* __restrict__ kh_g, const __nv_bfloat16* __restrict__ kl_g,
               const __nv_bfloat16* __restrict__ vth_g, const __nv_bfloat16* __restrict__ vtl_g,
               __nv_bfloat16* __restrict__ cex)
{
    extern __shared__ char fsm[];
    const unsigned int sb = (unsigned int)__cvta_generic_to_shared(fsm);
    const int tid  = threadIdx.x;
    const int lane = tid & 31;
    const int w    = tid >> 5;
    const int qt   = (S_ / 64 - 1) - blockIdx.x;   // longest-first (LPT)
    const int bh   = blockIdx.y;

    // preload Q tiles (hi + lo)
    {
        const size_t qoff = (((size_t)bh * S_) + qt * 64) * HD_;
#pragma unroll
        for (int i = 0; i < 8; i++) {
            const int idx = tid + i * 128;
            const int row = idx >> 4, c = idx & 15;
            const unsigned int off = (unsigned int)(row * 136 + c * 8) * 2;
            cpasync16(sb + FS_QH + off, qh_g + qoff + (size_t)row * HD_ + c * 8);
            cpasync16(sb + FS_QL + off, ql_g + qoff + (size_t)row * HD_ + c * 8);
        }
        cp_commit();
    }

    float oacc[16][4];
#pragma unroll
    for (int ni = 0; ni < 16; ni++)
#pragma unroll
        for (int e = 0; e < 4; e++) oacc[ni][e] = 0.0f;
    float m_i[2] = {-3.0e30f, -3.0e30f};
    float l_i[2] = {0.0f, 0.0f};

    const float SCALE = 0.08838834764831845f;   // 1/sqrt(128)

    for (int j = 0; j <= qt; j++) {
        {
            const size_t koff = (((size_t)bh * S_) + j * 64) * HD_;
            const size_t voff = ((size_t)bh * HD_) * S_ + j * 64;
#pragma unroll
            for (int i = 0; i < 8; i++) {
                const int idx = tid + i * 128;
                const int r16 = idx >> 4, c16 = idx & 15;
                const unsigned int offk = (unsigned int)(r16 * 136 + c16 * 8) * 2;
                cpasync16(sb + FS_KH + offk, kh_g + koff + (size_t)r16 * HD_ + c16 * 8);
                cpasync16(sb + FS_KL + offk, kl_g + koff + (size_t)r16 * HD_ + c16 * 8);
                const int r8 = idx >> 3, c8 = idx & 7;
                const unsigned int offv = (unsigned int)(r8 * 72 + c8 * 8) * 2;
                cpasync16(sb + FS_VH + offv, vth_g + voff + (size_t)r8 * S_ + c8 * 8);
                cpasync16(sb + FS_VL + offv, vtl_g + voff + (size_t)r8 * S_ + c8 * 8);
            }
            cp_commit();
        }
        asm volatile("cp.async.wait_group 0;\n");
        __syncthreads();

        // ---- scores: S = Qh·Kh^T + Ql·Kh^T + Qh·Kl^T ----
        float sreg[8][4];
#pragma unroll
        for (int ni = 0; ni < 8; ni++)
#pragma unroll
            for (int e = 0; e < 4; e++) sreg[ni][e] = 0.0f;

#pragma unroll
        for (int kt = 0; kt < 8; kt++) {
            unsigned int qfh[4], qfl[4], bfh[8][2], bfl[8][2];
            const int arow = w * 16 + (lane & 15);
            const unsigned int aoff = (unsigned int)(arow * 136 + kt * 16 + (lane >> 4) * 8) * 2;
            ldm_x4(qfh[0], qfh[1], qfh[2], qfh[3], sb + FS_QH + aoff);
            ldm_x4(qfl[0], qfl[1], qfl[2], qfl[3], sb + FS_QL + aoff);
#pragma unroll
            for (int p = 0; p < 4; p++) {
                const int nrow = p * 16 + (lane & 7) + ((lane >> 4) << 3);
                const unsigned int boff =
                    (unsigned int)(nrow * 136 + kt * 16 + ((lane >> 3) & 1) * 8) * 2;
                ldm_x4(bfh[2*p][0], bfh[2*p][1], bfh[2*p+1][0], bfh[2*p+1][1], sb + FS_KH + boff);
                ldm_x4(bfl[2*p][0], bfl[2*p][1], bfl[2*p+1][0], bfl[2*p+1][1], sb + FS_KL + boff);
            }
#pragma unroll
            for (int ni = 0; ni < 8; ni++) mma_bf16(sreg[ni], qfh, bfh[ni]);
#pragma unroll
            for (int ni = 0; ni < 8; ni++) mma_bf16(sreg[ni], qfl, bfh[ni]);
#pragma unroll
            for (int ni = 0; ni < 8; ni++) mma_bf16(sreg[ni], qfh, bfl[ni]);
        }

        // ---- scale + causal mask ----
        const bool diag = (j == qt);
        const int r0 = lane >> 2;
        const int c0 = (lane & 3) << 1;
#pragma unroll
        for (int ni = 0; ni < 8; ni++)
#pragma unroll
            for (int e = 0; e < 4; e++) {
                sreg[ni][e] *= SCALE;
                if (diag) {
                    const int qrow = w * 16 + r0 + ((e >> 1) << 3);
                    const int kcol = ni * 8 + c0 + (e & 1);
                    if (kcol > qrow) sreg[ni][e] = -1.0e30f;
                }
            }

        // ---- online softmax ----
        float corr[2];
#pragma unroll
        for (int h2 = 0; h2 < 2; h2++) {
            const int e0 = h2 * 2;
            float mloc = -3.0e30f;
#pragma unroll
            for (int ni = 0; ni < 8; ni++)
                mloc = fmaxf(mloc, fmaxf(sreg[ni][e0], sreg[ni][e0 + 1]));
            mloc = fmaxf(mloc, __shfl_xor_sync(0xffffffffu, mloc, 1));
            mloc = fmaxf(mloc, __shfl_xor_sync(0xffffffffu, mloc, 2));
            const float mnew = fmaxf(m_i[h2], mloc);
            corr[h2] = __expf(m_i[h2] - mnew);
            m_i[h2] = mnew;
            float lloc = 0.0f;
#pragma unroll
            for (int ni = 0; ni < 8; ni++) {
                const float p0 = __expf(sreg[ni][e0]     - mnew);
                const float p1 = __expf(sreg[ni][e0 + 1] - mnew);
                sreg[ni][e0] = p0; sreg[ni][e0 + 1] = p1;
                lloc += p0 + p1;
            }
            lloc += __shfl_xor_sync(0xffffffffu, lloc, 1);
            lloc += __shfl_xor_sync(0xffffffffu, lloc, 2);
            l_i[h2] = l_i[h2] * corr[h2] + lloc;
        }
#pragma unroll
        for (int ni = 0; ni < 16; ni++)
#pragma unroll
            for (int e = 0; e < 4; e++) oacc[ni][e] *= corr[e >> 1];

        // ---- repack P into A-fragments (hi/lo) ----
        unsigned int pah[4][4], pal[4][4];
#pragma unroll
        for (int t = 0; t < 4; t++) {
#pragma unroll
            for (int rix = 0; rix < 4; rix++) {
                const int ni = 2 * t + (rix >> 1);
                const int eb = (rix & 1) * 2;
                pah[t][rix] = pack_hi2(sreg[ni][eb], sreg[ni][eb + 1], pal[t][rix]);
            }
        }

        // ---- O += Ph·Vh + Pl·Vh + Ph·Vl ----
#pragma unroll
        for (int t = 0; t < 4; t++) {
            unsigned int bvh[16][2], bvl[16][2];
#pragma unroll
            for (int p = 0; p < 8; p++) {
                const int nrow = p * 16 + (lane & 7) + ((lane >> 4) << 3);
                const unsigned int boff =
                    (unsigned int)(nrow * 72 + t * 16 + ((lane >> 3) & 1) * 8) * 2;
                ldm_x4(bvh[2*p][0], bvh[2*p][1], bvh[2*p+1][0], bvh[2*p+1][1], sb + FS_VH + boff);
                ldm_x4(bvl[2*p][0], bvl[2*p][1], bvl[2*p+1][0], bvl[2*p+1][1], sb + FS_VL + boff);
            }
#pragma unroll
            for (int ni = 0; ni < 16; ni++) mma_bf16(oacc[ni], pah[t], bvh[ni]);
#pragma unroll
            for (int ni = 0; ni < 16; ni++) mma_bf16(oacc[ni], pal[t], bvh[ni]);
#pragma unroll
            for (int ni = 0; ni < 16; ni++) mma_bf16(oacc[ni], pah[t], bvl[ni]);
        }
        __syncthreads();   // before next j overwrites K/V smem
    }

    // ---- epilogue: write cex (hi|lo|hi) directly, packed 4B stores ----
    const float linv[2] = {1.0f / l_i[0], 1.0f / l_i[1]};
    const int b = bh >> 4;
    const int h = bh & (NH_ - 1);
    const int d0base = (lane & 3) << 1;
#pragma unroll
    for (int ni = 0; ni < 16; ni++) {
#pragma unroll
        for (int half = 0; half < 2; half++) {
            const int e0 = half * 2;
            const int qrow = qt * 64 + w * 16 + (lane >> 2) + half * 8;
            const int d0 = ni * 8 + d0base;
            const float v0 = oacc[ni][e0]     * linv[half];
            const float v1 = oacc[ni][e0 + 1] * linv[half];
            unsigned int lo;
            const unsigned int hi = pack_hi2(v0, v1, lo);
            __nv_bfloat16* dst =
                cex + ((size_t)b * S_ + qrow) * KEX_ + h * HD_ + d0;
            *(unsigned int*)(dst)          = hi;
            *(unsigned int*)(dst + K_)     = lo;
            *(unsigned int*)(dst + 2 * K_) = hi;
        }
    }
}

// ---------------------------------------------------------------------------
extern "C" void kernel_launch(void* const* d_in, const int* in_sizes, int n_in,
                              void* d_out, int out_size)
{
    const float* hs  = (const float*)d_in[0];
    // d_in[1] = attention_mask: deterministically causal, applied analytically
    const int*   pos = (const int*)d_in[2];
    const float* Wq  = (const float*)d_in[3];
    const float* Wk  = (const float*)d_in[4];
    const float* Wv  = (const float*)d_in[5];
    const float* Wo  = (const float*)d_in[6];
    float* out = (float*)d_out;

    float *q, *k, *v;
    __nv_bfloat16 *aex, *cex, *wqe, *wke, *wve, *woe;
    __nv_bfloat16 *qh, *ql, *kh, *kl, *vth, *vtl;
    cudaGetSymbolAddress((void**)&q,   g_q);
    cudaGetSymbolAddress((void**)&k,   g_k);
    cudaGetSymbolAddress((void**)&v,   g_v);
    cudaGetSymbolAddress((void**)&aex, g_aex);
    cudaGetSymbolAddress((void**)&cex, g_cex);
    cudaGetSymbolAddress((void**)&wqe, g_wqe);
    cudaGetSymbolAddress((void**)&wke, g_wke);
    cudaGetSymbolAddress((void**)&wve, g_wve);
    cudaGetSymbolAddress((void**)&woe, g_woe);
    cudaGetSymbolAddress((void**)&qh,  g_qh);
    cudaGetSymbolAddress((void**)&ql,  g_ql);
    cudaGetSymbolAddress((void**)&kh,  g_kh);
    cudaGetSymbolAddress((void**)&kl,  g_kl);
    cudaGetSymbolAddress((void**)&vth, g_vth);
    cudaGetSymbolAddress((void**)&vtl, g_vtl);

    const int nW8 = (HID_ * K_) / 8;
    // one launch: 4 weights + hidden states (8 elems/thread, 16B stores)
    split_all<<<dim3((nW8 + 255) / 256, 5), 256>>>(hs, Wq, Wk, Wv, Wo,
                                                   aex, wqe, wke, wve, woe, nW8);

    static bool attr_set = false;
    if (!attr_set) {
        cudaFuncSetAttribute(gemm_qkv,  cudaFuncAttributeMaxDynamicSharedMemorySize, GEMM_SMEM);
        cudaFuncSetAttribute(gemm_bf16, cudaFuncAttributeMaxDynamicSharedMemorySize, GEMM_SMEM);
        cudaFuncSetAttribute(flash_mma, cudaFuncAttributeMaxDynamicSharedMemorySize, FSMEM_TOTAL);
        attr_set = true;
    }

    // fused QKV projection: one launch, grid (48, 32)
    gemm_qkv<<<dim3(3 * HID_ / GBN, M_ / GBM), 256, GEMM_SMEM>>>(
        aex, wqe, wke, wve, q, k, v);

    const int rope_total = B_ * NH_ * S_ * 16;
    rope_split<<<(rope_total + 255) / 256, 256>>>(q, k, pos, qh, ql, kh, kl);

    vsplit_t<<<dim3(S_ / 32, HD_ / 32, B_ * NH_), dim3(32, 8)>>>(v, vth, vtl);

    // flash attention writes cex (expanded) directly
    flash_mma<<<dim3(S_ / 64, B_ * NH_), 128, FSMEM_TOTAL>>>(qh, ql, kh, kl, vth, vtl, cex);

    gemm_bf16<<<dim3(HID_ / GBN, M_ / GBM), 256, GEMM_SMEM>>>(cex, woe, out, HID_, KEX_);
}